// round 12
// baseline (speedup 1.0000x reference)
#include <cuda_runtime.h>
#include <cuda_fp16.h>
#include <cstdint>
#include <cstring>

#define NIMG 512
#define HW   1024

// ----------------------------------------------------------------------------
// scratch (device globals; no runtime allocation)
// ----------------------------------------------------------------------------
__device__ __half    g_kf16[(size_t)NIMG * HW * 8];    // latents fp16 NHWC8
__device__ __half    g_h[(size_t)NIMG * HW * 64];      // fp16 NHWC64 (permuted)
__device__ __half    g_tmp[(size_t)NIMG * HW * 64];    // fp16 NHWC64 (permuted)
__device__ uint32_t  g_wfrag[131072];                  // layers 1-5 B frags
__device__ uint32_t  g_wfold[(size_t)NIMG * 4608];     // per-image conv_in B frags
__device__ float     g_sfold[(size_t)NIMG * 576];      // per-image alpha border terms

#define WOFF_HID0 9216
#define WOFF_OUT  (9216 + 4 * 18432)   // 82944

__device__ __forceinline__ void mma_f16(float d[4], uint32_t a0, uint32_t a1,
                                        uint32_t a2, uint32_t a3,
                                        uint32_t b0, uint32_t b1) {
    asm volatile(
        "mma.sync.aligned.m16n8k16.row.col.f32.f16.f16.f32 "
        "{%0,%1,%2,%3}, {%4,%5,%6,%7}, {%8,%9}, {%0,%1,%2,%3};"
        : "+f"(d[0]), "+f"(d[1]), "+f"(d[2]), "+f"(d[3])
        : "r"(a0), "r"(a1), "r"(a2), "r"(a3), "r"(b0), "r"(b1));
}

__device__ __forceinline__ void cp_async16(uint32_t dst, const void* src, uint32_t srcsize) {
    asm volatile("cp.async.ca.shared.global [%0], [%1], 16, %2;"
                 :: "r"(dst), "l"(src), "r"(srcsize) : "memory");
}
__device__ __forceinline__ void cp_commit() {
    asm volatile("cp.async.commit_group;" ::: "memory");
}
__device__ __forceinline__ void cp_wait0() {
    asm volatile("cp.async.wait_group 0;" ::: "memory");
}
__device__ __forceinline__ void cp_wait1() {
    asm volatile("cp.async.wait_group 1;" ::: "memory");
}
__device__ __forceinline__ uint32_t smem_u32(const void* p) {
    uint32_t a;
    asm("{ .reg .u64 t; cvta.to.shared.u64 t, %1; cvt.u32.u64 %0, t; }"
        : "=r"(a) : "l"(p));
    return a;
}
__device__ __forceinline__ uint32_t h2u(__half2 h) {
    uint32_t u; memcpy(&u, &h, 4); return u;
}

// sort idx + derive segment for image (b,t)
__device__ __forceinline__ void seg_params(const int* __restrict__ idx, int b, int t,
                                           int& t0, int& t1, float& a, float& araw) {
    int v[9];
#pragma unroll
    for (int k = 0; k < 9; k++) v[k] = idx[b * 9 + k];
#pragma unroll
    for (int i = 1; i < 9; i++) {
        int key = v[i]; int j = i - 1;
        while (j >= 0 && v[j] > key) { v[j + 1] = v[j]; j--; }
        v[j + 1] = key;
    }
    int cnt = 0;
#pragma unroll
    for (int k = 0; k < 9; k++) cnt += (v[k] <= t);
    int seg = min(max(cnt - 1, 0), 7);
    t0 = v[seg]; t1 = v[seg + 1];
    araw = (float)(t - t0) / (float)max(t1 - t0, 1);
    a = fminf(fmaxf(araw, 0.f), 1.f);
}

// ----------------------------------------------------------------------------
// kf convert: all latent frames fp32 NCHW -> fp16 per-pixel 8ch
// ----------------------------------------------------------------------------
__global__ __launch_bounds__(256)
void kf_kernel(const float* __restrict__ latents, __half* __restrict__ kf)
{
    const int fr = blockIdx.x;
    const int tid = threadIdx.x;
    const float* L = latents + (size_t)fr * 8 * HW;
#pragma unroll
    for (int j = 0; j < 4; j++) {
        const int p = tid + j * 256;
        uint32_t w[4];
#pragma unroll
        for (int q = 0; q < 4; q++)
            w[q] = h2u(__floats2half2_rn(L[(2*q) * HW + p], L[(2*q+1) * HW + p]));
        *(uint4*)(kf + ((size_t)fr * HW + p) * 8) = make_uint4(w[0], w[1], w[2], w[3]);
    }
}

// ----------------------------------------------------------------------------
// fold conv_in weights per image (see R11 notes)
// ----------------------------------------------------------------------------
__global__ __launch_bounds__(256)
void fold_kernel(const float* __restrict__ w_in, const int* __restrict__ idx,
                 uint32_t* __restrict__ wfold, float* __restrict__ sfold)
{
    const int n = blockIdx.x;
    const int tid = threadIdx.x;
    int t0, t1; float a, araw;
    seg_params(idx, n >> 7, n & 127, t0, t1, a, araw);

    __half* wh = (__half*)(wfold + (size_t)n * 4608);
    for (int i = tid; i < 4608; i += 256) {
        const int o   = i / 72;
        const int r   = i % 72;
        const int tap = r / 8;
        const int ci  = r % 8;
        const float W0 = w_in[(o * 25 + ci) * 9 + tap];
        const float W1 = w_in[(o * 25 + 8 + ci) * 9 + tap];
        const float W2 = w_in[(o * 25 + 16 + ci) * 9 + tap];
        const float U  = (1.f - a) * W0 + W1;
        const float V  = a * W0 + W2;
        const int kz0 = 2 * (ci >> 2) + 8 * ((ci >> 1) & 1) + (ci & 1);
#pragma unroll
        for (int h = 0; h < 2; h++) {
            const int k  = kz0 + 4 * h;
            const int hi = k >> 3, rem = k & 7, tt = rem >> 1, hf = rem & 1;
            const int lane = (o & 7) * 4 + tt;
            const int word = (o >> 5) * 2304 + (tap * 4 + ((o >> 3) & 3)) * 64 + lane * 2 + hi;
            wh[word * 2 + hf] = __float2half(h ? V : U);
        }
    }
    for (int i = tid; i < 576; i += 256) {
        const int o  = i / 9;
        const int cs = i % 9;
        const int cy = cs / 3, cx = cs % 3;
        float sum = 0.f;
#pragma unroll
        for (int dy = 0; dy < 3; dy++) {
            if ((cy == 0 && dy == 0) || (cy == 2 && dy == 2)) continue;
#pragma unroll
            for (int dx = 0; dx < 3; dx++) {
                if ((cx == 0 && dx == 0) || (cx == 2 && dx == 2)) continue;
                sum += w_in[(o * 25 + 24) * 9 + dy * 3 + dx];
            }
        }
        sfold[(size_t)n * 576 + cs * 64 + o] = a * sum;
    }
}

// ----------------------------------------------------------------------------
// weight prep (layers 1..5): OIHW fp32 -> f16 B-fragment layout
// ----------------------------------------------------------------------------
__global__ __launch_bounds__(256)
void wprep_kernel(const float* __restrict__ w1s, const float* __restrict__ w2s,
                  const float* __restrict__ w_out, uint32_t* __restrict__ wfrag)
{
    const int layer = blockIdx.x + 1;   // 1..4 hidden, 5 out
    const int tid = threadIdx.x;

    const float* w;
    int cin, cout, woff, nwords, chunks, ntb;
    if (layer <= 4) {
        const int blk = (layer - 1) >> 1;
        w = ((layer - 1) & 1) ? (w2s + (size_t)blk * 64 * 64 * 9)
                              : (w1s + (size_t)blk * 64 * 64 * 9);
        cin = 64; cout = 64; woff = WOFF_HID0 + (layer - 1) * 18432; nwords = 18432; chunks = 36; ntb = 4;
    } else {
        w = w_out; cin = 64; cout = 9;  woff = WOFF_OUT; nwords = 4608; chunks = 36; ntb = 2;
    }

    for (int i = tid; i < nwords; i += 256) wfrag[woff + i] = 0u;
    __syncthreads();

    __half* wh = (__half*)(wfrag);
    const int wtot = cout * cin * 9;
    for (int i = tid; i < wtot; i += 256) {
        const int tap = i % 9;
        const int ci  = (i / 9) % cin;
        const int co  = i / (9 * cin);
        const int cg  = ci >> 5;
        const int kin = ci & 31;
        const int g2  = kin >> 4;
        const int k16 = kin & 15;
        const int chunk = (cg * 9 + tap) * 2 + g2;
        const int hi  = k16 >> 3;
        const int rem = k16 & 7;
        const int tt  = rem >> 1;
        const int hf  = rem & 1;
        const int lane = (co & 7) * 4 + tt;
        int word;
        if (ntb == 4) {
            const int nhalf = co >> 5;
            const int nt4   = (co >> 3) & 3;
            word = woff + nhalf * chunks * 256 + (chunk * 4 + nt4) * 64 + lane * 2 + hi;
        } else {
            const int nt = co >> 3;
            word = woff + (chunk * 2 + nt) * 64 + lane * 2 + hi;
        }
        wh[word * 2 + hf] = __float2half(w[i]);
    }
}

// ----------------------------------------------------------------------------
// conv_in (fused prep): 16 real channels (z0|z1 from kf16), per-image folded
// weights, alpha border correction, SiLU, fp16 permuted NHWC64 out.
// ----------------------------------------------------------------------------
__global__ __launch_bounds__(256, 2)
void conv_in16(const __half* __restrict__ kf, const uint32_t* __restrict__ wfold,
               const float* __restrict__ sfold, const float* __restrict__ bias,
               __half* __restrict__ out, const int* __restrict__ idx)
{
    constexpr int NTB = 4;
    constexpr int BW  = 9 * NTB * 64;   // 2304 words
    extern __shared__ uint32_t smem[];
    uint32_t* b_s = smem;
    uint32_t* X_s = smem + BW;

    const int tid   = threadIdx.x;
    const int wid   = tid >> 5;
    const int lane  = tid & 31;
    const int n     = blockIdx.x;
    const int nhalf = blockIdx.y;
    const int tx    = lane >> 2;
    const int kq2   = (lane & 3) * 2;
    const int ch0   = nhalf * 32;

    int t0, t1; float a, araw;
    seg_params(idx, n >> 7, n & 127, t0, t1, a, araw);
    const int fb = n >> 7;
    const char* kf0 = (const char*)(kf + ((size_t)(fb * 128 + t0)) * HW * 8);
    const char* kf1 = (const char*)(kf + ((size_t)(fb * 128 + t1)) * HW * 8);
    const char* kfp = (tid & 1) ? kf1 : kf0;

    const uint32_t bs_u = smem_u32(b_s);
    const uint32_t xs_u = smem_u32(X_s);

    const uint32_t* wsrc = wfold + (size_t)n * 4608 + nhalf * 2304;
    for (int i = tid; i < BW / 4; i += 256)
        cp_async16(bs_u + i * 16, wsrc + i * 4, 16);

    uint32_t s_dst[5];
#pragma unroll
    for (int q = 0; q < 5; q++) {
        const int i = tid + q * 256;
        const int px = i >> 1, part = i & 1;
        s_dst[q] = (uint32_t)(px * 32 + part * 16);
    }

    auto stage_tile = [&](int tile) {
#pragma unroll
        for (int q = 0; q < 5; q++) {
            const int i = tid + q * 256;
            if (q < 4 || tid < 200) {
                const int px = i >> 1;
                const int rr = px / 34;
                const int gx = px - rr * 34 - 1;
                const int gy = tile * 16 - 1 + rr;
                const bool ok = (gx >= 0) && (gx < 32) && (gy >= 0) && (gy < 32)
                                && (i < 1224);
                const int pix = ok ? (gy * 32 + gx) : 0;
                cp_async16(xs_u + tile * 19584 + s_dst[q], kfp + (size_t)pix * 16,
                           ok ? 16u : 0u);
            }
        }
        cp_commit();
    };

    stage_tile(0);
    stage_tile(1);

    float bv[NTB][2];
#pragma unroll
    for (int nt = 0; nt < NTB; nt++) {
        bv[nt][0] = bias[ch0 + nt * 8 + kq2];
        bv[nt][1] = bias[ch0 + nt * 8 + kq2 + 1];
    }
    const float* Sp = sfold + (size_t)n * 576;

#pragma unroll 1
    for (int tile = 0; tile < 2; tile++) {
        if (tile == 0) cp_wait1(); else cp_wait0();
        __syncthreads();

        float d[4][NTB][4];
#pragma unroll
        for (int f = 0; f < 4; f++)
#pragma unroll
            for (int nt = 0; nt < NTB; nt++)
#pragma unroll
                for (int q = 0; q < 4; q++) d[f][nt][q] = 0.f;

        const uint32_t* Xb = X_s + tile * 4896;

#pragma unroll
        for (int tap = 0; tap < 9; tap++) {
            const int dy = tap / 3, dx = tap - 3 * (tap / 3);
            const uint32_t* A = Xb + ((2 * wid + dy) * 34 + tx + dx) * 8 + kq2;
            const uint2 u0 = *(const uint2*)(A);
            const uint2 u1 = *(const uint2*)(A + 64);
            const uint2 u2 = *(const uint2*)(A + 128);
            const uint2 u3 = *(const uint2*)(A + 192);
            const uint2 u4 = *(const uint2*)(A + 272);
            const uint2 u5 = *(const uint2*)(A + 336);
            const uint2 u6 = *(const uint2*)(A + 400);
            const uint2 u7 = *(const uint2*)(A + 464);
            const uint32_t* bp = b_s + (size_t)tap * NTB * 64 + lane * 2;
#pragma unroll
            for (int nt = 0; nt < NTB; nt++) {
                const uint2 b = *(const uint2*)(bp + nt * 64);
                mma_f16(d[0][nt], u0.x, u1.x, u0.y, u1.y, b.x, b.y);
                mma_f16(d[1][nt], u2.x, u3.x, u2.y, u3.y, b.x, b.y);
                mma_f16(d[2][nt], u4.x, u5.x, u4.y, u5.y, b.x, b.y);
                mma_f16(d[3][nt], u6.x, u7.x, u6.y, u7.y, b.x, b.y);
            }
        }

#pragma unroll
        for (int f = 0; f < 4; f++) {
            const int gy  = tile * 16 + 2 * wid + (f >> 1);
            const int gx0 = ((f & 1) << 4) + tx;
            const int gx1 = gx0 + 8;
            const int cy  = (gy == 0) ? 0 : ((gy == 31) ? 2 : 1);
            const int cx0 = (gx0 == 0) ? 0 : ((gx0 == 31) ? 2 : 1);
            const int cx1 = (gx1 == 31) ? 2 : 1;
            const int base0 = (cy * 3 + cx0) * 64;
            const int base1 = (cy * 3 + cx1) * 64;
            const size_t gp0 = (size_t)n * HW + gy * 32 + gx0;
            const size_t gp1 = gp0 + 8;
#pragma unroll
            for (int nt = 0; nt < NTB; nt++) {
                const int c = ch0 + nt * 8 + kq2;
                float v00 = d[f][nt][0] + bv[nt][0] + Sp[base0 + c];
                float v01 = d[f][nt][1] + bv[nt][1] + Sp[base0 + c + 1];
                float v10 = d[f][nt][2] + bv[nt][0] + Sp[base1 + c];
                float v11 = d[f][nt][3] + bv[nt][1] + Sp[base1 + c + 1];
                v00 = __fdividef(v00, 1.f + __expf(-v00));
                v01 = __fdividef(v01, 1.f + __expf(-v01));
                v10 = __fdividef(v10, 1.f + __expf(-v10));
                v11 = __fdividef(v11, 1.f + __expf(-v11));
                const int g16 = c >> 4;
                const int cl  = c & 15;
                const int jl  = (((cl >> 3) & 1) << 1) | (((cl >> 1) & 3) << 2);
                __half2* oh = (__half2*)out;
                oh[(gp0 * 64 + g16 * 16 + jl) >> 1] = __floats2half2_rn(v00, v01);
                oh[(gp1 * 64 + g16 * 16 + jl) >> 1] = __floats2half2_rn(v10, v11);
            }
        }
        if (tile == 0) __syncthreads();
    }
}

// ----------------------------------------------------------------------------
// PERSISTENT hidden/out conv: mma.sync m16n8k16, M64xN=NTB*8 per warp.
// Work unit = image-tile (1024 units per nhalf); CTA strides over units with
// the 3-buffer slab pipeline flowing continuously across units. B staged once.
// FINAL fuses z_hat/conf finalize into the epilogue.
// ----------------------------------------------------------------------------
template<int NTB, bool SILU, bool RESID, bool FINAL>
__global__ __launch_bounds__(256, 2)
void conv_mma(const void* __restrict__ in_v, const uint32_t* __restrict__ wfrag,
              const float* __restrict__ bias, void* __restrict__ out_v,
              const void* __restrict__ resid_v,
              const float* __restrict__ latents, const int* __restrict__ idx)
{
    constexpr int CIN    = 64;
    constexpr int CHUNKS = 36;
    constexpr int BW     = CHUNKS * NTB * 64;
    constexpr int NU     = 1024;                 // image-tile units
    constexpr bool F16OUT = (NTB == 4);

    extern __shared__ uint32_t smem[];
    uint32_t* b_s = smem;
    uint32_t* X_s = smem + BW;

    const int tid    = threadIdx.x;
    const int wid    = tid >> 5;
    const int lane   = tid & 31;
    const int bx     = blockIdx.x;
    const int stride = gridDim.x;
    const int nhalf  = blockIdx.y;
    const int tx     = lane >> 2;
    const int kq2    = (lane & 3) * 2;
    const int ch0    = F16OUT ? nhalf * 32 : 0;

    const int J     = (NU - 1 - bx) / stride + 1;
    const int totls = J * 4;

    const uint32_t bs_u = smem_u32(b_s);
    const uint32_t xs_u = smem_u32(X_s);

    // B fragments: once per CTA (joins cp group 0)
    const uint32_t* wsrc = wfrag + (size_t)nhalf * CHUNKS * NTB * 64;
    for (int i = tid; i < BW / 4; i += 256)
        cp_async16(bs_u + i * 16, wsrc + i * 4, 16);

    uint32_t s_dst[5];
#pragma unroll
    for (int q = 0; q < 5; q++) {
        const int i = tid + q * 256;
        const int px = i >> 1, part = i & 1;
        s_dst[q] = (uint32_t)(px * 32 + part * 16);
    }
    int s_src[5];
    uint32_t okb = 0;
    int cached_j = -1;
    const char* in_cur = nullptr;

    auto stage_slab = [&](int ls) {
        const int j = ls >> 2;
        const int k = ls & 3;
        if (j != cached_j) {
            cached_j = j;
            const int u    = bx + j * stride;
            const int tile = u & 1;
            in_cur = (const char*)in_v + (size_t)(u >> 1) * (HW * CIN * 2);
            okb = 0;
#pragma unroll
            for (int q = 0; q < 5; q++) {
                const int i = tid + q * 256;
                const int px = i >> 1, part = i & 1;
                const int rr = px / 34;
                const int gx = px - rr * 34 - 1;
                const int gy = tile * 16 - 1 + rr;
                const bool ok = (gx >= 0) && (gx < 32) && (gy >= 0) && (gy < 32)
                                && (i < 1224);
                const int pix = ok ? (gy * 32 + gx) : 0;
                s_src[q] = pix * CIN * 2 + part * 16;
                okb |= (ok ? 1u : 0u) << q;
            }
        }
        const uint32_t xoff = (uint32_t)((ls % 3) * 19584);
#pragma unroll
        for (int q = 0; q < 5; q++) {
            if (q < 4 || tid < 200)
                cp_async16(xs_u + xoff + s_dst[q], in_cur + s_src[q] + k * 32,
                           ((okb >> q) & 1) ? 16u : 0u);
        }
        cp_commit();
    };

    stage_slab(0);
    if (totls > 1) stage_slab(1);

    float bv[NTB][2];
#pragma unroll
    for (int nt = 0; nt < NTB; nt++) {
        const int bi = ch0 + nt * 8 + kq2;
        bv[nt][0] = (F16OUT || bi     < 9) ? bias[bi]     : 0.f;
        bv[nt][1] = (F16OUT || bi + 1 < 9) ? bias[bi + 1] : 0.f;
    }

    float d[4][NTB][4];

#pragma unroll 1
    for (int ls = 0; ls < totls; ls++) {
        const int k = ls & 3;

        if (ls + 1 < totls) cp_wait1(); else cp_wait0();
        __syncthreads();
        if (ls + 2 < totls) stage_slab(ls + 2);

        if (k == 0) {
#pragma unroll
            for (int f = 0; f < 4; f++)
#pragma unroll
                for (int nt = 0; nt < NTB; nt++)
#pragma unroll
                    for (int q = 0; q < 4; q++) d[f][nt][q] = 0.f;
        }

        const uint32_t* Xb = X_s + (ls % 3) * 4896;
        const int cbase = (k >> 1) * 18 + (k & 1);

#pragma unroll
        for (int tap = 0; tap < 9; tap++) {
            const int dy = tap / 3, dx = tap - 3 * (tap / 3);
            const uint32_t* A = Xb + ((2 * wid + dy) * 34 + tx + dx) * 8 + kq2;
            const uint2 u0 = *(const uint2*)(A);
            const uint2 u1 = *(const uint2*)(A + 64);
            const uint2 u2 = *(const uint2*)(A + 128);
            const uint2 u3 = *(const uint2*)(A + 192);
            const uint2 u4 = *(const uint2*)(A + 272);
            const uint2 u5 = *(const uint2*)(A + 336);
            const uint2 u6 = *(const uint2*)(A + 400);
            const uint2 u7 = *(const uint2*)(A + 464);
            const uint32_t* bp = b_s + (size_t)(cbase + tap * 2) * NTB * 64 + lane * 2;
#pragma unroll
            for (int nt = 0; nt < NTB; nt++) {
                const uint2 b = *(const uint2*)(bp + nt * 64);
                mma_f16(d[0][nt], u0.x, u1.x, u0.y, u1.y, b.x, b.y);
                mma_f16(d[1][nt], u2.x, u3.x, u2.y, u3.y, b.x, b.y);
                mma_f16(d[2][nt], u4.x, u5.x, u4.y, u5.y, b.x, b.y);
                mma_f16(d[3][nt], u6.x, u7.x, u6.y, u7.y, b.x, b.y);
            }
        }

        if (k == 3) {
            const int u    = bx + (ls >> 2) * stride;
            const int n    = u >> 1;
            const int tile = u & 1;

            float fs_a = 0.f, fs_s = 0.f;
            bool  fs_int = false;
            const float* L0f = nullptr;
            const float* L1f = nullptr;
            if constexpr (FINAL) {
                int t0, t1; float araw;
                seg_params(idx, n >> 7, n & 127, t0, t1, fs_a, araw);
                fs_s   = fs_a * (1.f - fs_a);
                fs_int = (araw > 0.f) && (araw < 1.f);
                L0f = latents + ((size_t)((n >> 7) * 128 + t0)) * 8 * HW;
                L1f = latents + ((size_t)((n >> 7) * 128 + t1)) * 8 * HW;
            }

#pragma unroll
            for (int f = 0; f < 4; f++) {
                const int gy = tile * 16 + 2 * wid + (f >> 1);
                const int gx = ((f & 1) << 4) + tx;
                const int p0i = gy * 32 + gx;
                const size_t gp0 = (size_t)n * HW + p0i;
                const size_t gp1 = gp0 + 8;

                if constexpr (FINAL) {
                    float* outp = (float*)out_v;
#pragma unroll
                    for (int e = 0; e < 2; e++) {
                        const int c = kq2 + e;
                        const float r0 = d[f][0][e]     + bv[0][e];
                        const float r1 = d[f][0][2 + e] + bv[0][e];
                        const float zb0 = (1.f - fs_a) * L0f[c * HW + p0i]
                                        + fs_a * L1f[c * HW + p0i];
                        const float zb1 = (1.f - fs_a) * L0f[c * HW + p0i + 8]
                                        + fs_a * L1f[c * HW + p0i + 8];
                        outp[((size_t)n * 8 + c) * HW + p0i]     = zb0 + fs_s * r0;
                        outp[((size_t)n * 8 + c) * HW + p0i + 8] = zb1 + fs_s * r1;
                    }
                    if (kq2 == 0) {
                        const float l0 = d[f][1][0] + bv[1][0];
                        const float l1 = d[f][1][2] + bv[1][0];
                        float c0 = 1.f, c1 = 1.f;
                        if (fs_int) {
                            c0 = 1.f - __fdividef(1.f, 1.f + __expf(-l0));
                            c1 = 1.f - __fdividef(1.f, 1.f + __expf(-l1));
                            c0 = fminf(fmaxf(c0, 0.f), 1.f);
                            c1 = fminf(fmaxf(c1, 0.f), 1.f);
                        }
                        float* cf = outp + (size_t)NIMG * 8 * HW + (size_t)n * HW;
                        cf[p0i]     = c0;
                        cf[p0i + 8] = c1;
                    }
                } else {
#pragma unroll
                    for (int nt = 0; nt < NTB; nt++) {
                        const int c = ch0 + nt * 8 + kq2;
                        float v00 = d[f][nt][0] + bv[nt][0];
                        float v01 = d[f][nt][1] + bv[nt][1];
                        float v10 = d[f][nt][2] + bv[nt][0];
                        float v11 = d[f][nt][3] + bv[nt][1];
                        if (SILU) {
                            v00 = __fdividef(v00, 1.f + __expf(-v00));
                            v01 = __fdividef(v01, 1.f + __expf(-v01));
                            v10 = __fdividef(v10, 1.f + __expf(-v10));
                            v11 = __fdividef(v11, 1.f + __expf(-v11));
                        }
                        const int g16 = c >> 4;
                        const int cl  = c & 15;
                        const int jl  = (((cl >> 3) & 1) << 1) | (((cl >> 1) & 3) << 2);
                        const size_t h0 = gp0 * 64 + g16 * 16 + jl;
                        const size_t h1 = gp1 * 64 + g16 * 16 + jl;
                        if (RESID) {
                            const __half2* rh = (const __half2*)resid_v;
                            const float2 r0 = __half22float2(rh[h0 >> 1]);
                            const float2 r1 = __half22float2(rh[h1 >> 1]);
                            v00 += r0.x; v01 += r0.y; v10 += r1.x; v11 += r1.y;
                        }
                        __half2* oh = (__half2*)out_v;
                        oh[h0 >> 1] = __floats2half2_rn(v00, v01);
                        oh[h1 >> 1] = __floats2half2_rn(v10, v11);
                    }
                }
            }
        }
    }
}

// ----------------------------------------------------------------------------
// launch
// ----------------------------------------------------------------------------
extern "C" void kernel_launch(void* const* d_in, const int* in_sizes, int n_in,
                              void* d_out, int out_size)
{
    const float* latents = (const float*)d_in[0];
    const int*   idx     = (const int*)d_in[1];
    const float* w_in    = (const float*)d_in[2];
    const float* b_in    = (const float*)d_in[3];
    const float* w1s     = (const float*)d_in[4];
    const float* b1s     = (const float*)d_in[5];
    const float* w2s     = (const float*)d_in[6];
    const float* b2s     = (const float*)d_in[7];
    const float* w_out   = (const float*)d_in[8];
    const float* b_out   = (const float*)d_in[9];
    float* outp = (float*)d_out;

    __half *kf, *h, *tmp;
    uint32_t *wfrag, *wfold;
    float* sfold;
    cudaGetSymbolAddress((void**)&kf,    g_kf16);
    cudaGetSymbolAddress((void**)&h,     g_h);
    cudaGetSymbolAddress((void**)&tmp,   g_tmp);
    cudaGetSymbolAddress((void**)&wfrag, g_wfrag);
    cudaGetSymbolAddress((void**)&wfold, g_wfold);
    cudaGetSymbolAddress((void**)&sfold, g_sfold);

    constexpr int SM_IN16 = ( 2304 + 3 * 4896) * 4;
    constexpr int SM_HID  = ( 9216 + 3 * 4896) * 4;   // 95,616
    constexpr int SM_OUT  = ( 4608 + 3 * 4896) * 4;   // 77,184

    cudaFuncSetAttribute(conv_in16,
                         cudaFuncAttributeMaxDynamicSharedMemorySize, SM_IN16);
    cudaFuncSetAttribute(conv_mma<4, true,  false, false>,
                         cudaFuncAttributeMaxDynamicSharedMemorySize, SM_HID);
    cudaFuncSetAttribute(conv_mma<4, false, true,  false>,
                         cudaFuncAttributeMaxDynamicSharedMemorySize, SM_HID);
    cudaFuncSetAttribute(conv_mma<2, false, false, true>,
                         cudaFuncAttributeMaxDynamicSharedMemorySize, SM_OUT);

    kf_kernel<<<NIMG, 256>>>(latents, kf);
    fold_kernel<<<NIMG, 256>>>(w_in, idx, wfold, sfold);
    wprep_kernel<<<5, 256>>>(w1s, w2s, w_out, wfrag);

    // conv_in (fused prep): z0|z1 16ch -> 64, SiLU
    conv_in16<<<dim3(NIMG, 2), 256, SM_IN16>>>(kf, wfold, sfold, b_in, h, idx);

    // persistent hidden layers: grid (148, 2) = exactly the concurrent slots
    for (int blk = 0; blk < 2; blk++) {
        const float* b1 = b1s + blk * 64;
        const float* b2 = b2s + blk * 64;
        conv_mma<4, true, false, false><<<dim3(148, 2), 256, SM_HID>>>(
            h, wfrag + WOFF_HID0 + (2 * blk) * 18432, b1, tmp, nullptr, nullptr, nullptr);
        conv_mma<4, false, true, false><<<dim3(148, 2), 256, SM_HID>>>(
            tmp, wfrag + WOFF_HID0 + (2 * blk + 1) * 18432, b2, h, h, nullptr, nullptr);
    }

    // conv_out: 64 -> 9, fused finalize -> d_out (persistent, grid 296)
    conv_mma<2, false, false, true><<<dim3(296, 1), 256, SM_OUT>>>(
        h, wfrag + WOFF_OUT, b_out, outp, nullptr, latents, idx);
}

// round 13
// speedup vs baseline: 1.0148x; 1.0148x over previous
#include <cuda_runtime.h>
#include <cuda_fp16.h>
#include <cstdint>
#include <cstring>

#define NIMG 512
#define HW   1024

// ----------------------------------------------------------------------------
// scratch (device globals; no runtime allocation)
// ----------------------------------------------------------------------------
__device__ __half    g_kf16[(size_t)NIMG * HW * 8];    // latents fp16 NHWC8
__device__ __half    g_h[(size_t)NIMG * HW * 64];      // fp16 NHWC64 (permuted)
__device__ __half    g_tmp[(size_t)NIMG * HW * 64];    // fp16 NHWC64 (permuted)
__device__ uint32_t  g_wfrag[131072];                  // layers 1-5 B frags
__device__ uint32_t  g_wfold[(size_t)NIMG * 4608];     // per-image conv_in B frags
__device__ float     g_sfold[(size_t)NIMG * 576];      // per-image alpha border terms

#define WOFF_HID0 9216
#define WOFF_OUT  (9216 + 4 * 18432)   // 82944

__device__ __forceinline__ void mma_f16(float d[4], uint32_t a0, uint32_t a1,
                                        uint32_t a2, uint32_t a3,
                                        uint32_t b0, uint32_t b1) {
    asm volatile(
        "mma.sync.aligned.m16n8k16.row.col.f32.f16.f16.f32 "
        "{%0,%1,%2,%3}, {%4,%5,%6,%7}, {%8,%9}, {%0,%1,%2,%3};"
        : "+f"(d[0]), "+f"(d[1]), "+f"(d[2]), "+f"(d[3])
        : "r"(a0), "r"(a1), "r"(a2), "r"(a3), "r"(b0), "r"(b1));
}

__device__ __forceinline__ void cp_async16(uint32_t dst, const void* src, uint32_t srcsize) {
    asm volatile("cp.async.ca.shared.global [%0], [%1], 16, %2;"
                 :: "r"(dst), "l"(src), "r"(srcsize) : "memory");
}
__device__ __forceinline__ void cp_commit() {
    asm volatile("cp.async.commit_group;" ::: "memory");
}
__device__ __forceinline__ void cp_wait0() {
    asm volatile("cp.async.wait_group 0;" ::: "memory");
}
__device__ __forceinline__ void cp_wait1() {
    asm volatile("cp.async.wait_group 1;" ::: "memory");
}
__device__ __forceinline__ uint32_t smem_u32(const void* p) {
    uint32_t a;
    asm("{ .reg .u64 t; cvta.to.shared.u64 t, %1; cvt.u32.u64 %0, t; }"
        : "=r"(a) : "l"(p));
    return a;
}
__device__ __forceinline__ uint32_t h2u(__half2 h) {
    uint32_t u; memcpy(&u, &h, 4); return u;
}

// sort idx + derive segment for image (b,t)
__device__ __forceinline__ void seg_params(const int* __restrict__ idx, int b, int t,
                                           int& t0, int& t1, float& a, float& araw) {
    int v[9];
#pragma unroll
    for (int k = 0; k < 9; k++) v[k] = idx[b * 9 + k];
#pragma unroll
    for (int i = 1; i < 9; i++) {
        int key = v[i]; int j = i - 1;
        while (j >= 0 && v[j] > key) { v[j + 1] = v[j]; j--; }
        v[j + 1] = key;
    }
    int cnt = 0;
#pragma unroll
    for (int k = 0; k < 9; k++) cnt += (v[k] <= t);
    int seg = min(max(cnt - 1, 0), 7);
    t0 = v[seg]; t1 = v[seg + 1];
    araw = (float)(t - t0) / (float)max(t1 - t0, 1);
    a = fminf(fmaxf(araw, 0.f), 1.f);
}

// ----------------------------------------------------------------------------
// kf convert: all latent frames fp32 NCHW -> fp16 per-pixel 8ch
// ----------------------------------------------------------------------------
__global__ __launch_bounds__(256)
void kf_kernel(const float* __restrict__ latents, __half* __restrict__ kf)
{
    const int fr = blockIdx.x;
    const int tid = threadIdx.x;
    const float* L = latents + (size_t)fr * 8 * HW;
#pragma unroll
    for (int j = 0; j < 4; j++) {
        const int p = tid + j * 256;
        uint32_t w[4];
#pragma unroll
        for (int q = 0; q < 4; q++)
            w[q] = h2u(__floats2half2_rn(L[(2*q) * HW + p], L[(2*q+1) * HW + p]));
        *(uint4*)(kf + ((size_t)fr * HW + p) * 8) = make_uint4(w[0], w[1], w[2], w[3]);
    }
}

// ----------------------------------------------------------------------------
// fold conv_in weights per image:
//   U = (1-a)W0 + W1 on z0 slots, V = a W0 + W2 on z1 slots, alpha border S.
// ----------------------------------------------------------------------------
__global__ __launch_bounds__(256)
void fold_kernel(const float* __restrict__ w_in, const int* __restrict__ idx,
                 uint32_t* __restrict__ wfold, float* __restrict__ sfold)
{
    const int n = blockIdx.x;
    const int tid = threadIdx.x;
    int t0, t1; float a, araw;
    seg_params(idx, n >> 7, n & 127, t0, t1, a, araw);

    __half* wh = (__half*)(wfold + (size_t)n * 4608);
    for (int i = tid; i < 4608; i += 256) {
        const int o   = i / 72;
        const int r   = i % 72;
        const int tap = r / 8;
        const int ci  = r % 8;
        const float W0 = w_in[(o * 25 + ci) * 9 + tap];
        const float W1 = w_in[(o * 25 + 8 + ci) * 9 + tap];
        const float W2 = w_in[(o * 25 + 16 + ci) * 9 + tap];
        const float U  = (1.f - a) * W0 + W1;
        const float V  = a * W0 + W2;
        const int kz0 = 2 * (ci >> 2) + 8 * ((ci >> 1) & 1) + (ci & 1);
#pragma unroll
        for (int h = 0; h < 2; h++) {
            const int k  = kz0 + 4 * h;
            const int hi = k >> 3, rem = k & 7, tt = rem >> 1, hf = rem & 1;
            const int lane = (o & 7) * 4 + tt;
            const int word = (o >> 5) * 2304 + (tap * 4 + ((o >> 3) & 3)) * 64 + lane * 2 + hi;
            wh[word * 2 + hf] = __float2half(h ? V : U);
        }
    }
    for (int i = tid; i < 576; i += 256) {
        const int o  = i / 9;
        const int cs = i % 9;
        const int cy = cs / 3, cx = cs % 3;
        float sum = 0.f;
#pragma unroll
        for (int dy = 0; dy < 3; dy++) {
            if ((cy == 0 && dy == 0) || (cy == 2 && dy == 2)) continue;
#pragma unroll
            for (int dx = 0; dx < 3; dx++) {
                if ((cx == 0 && dx == 0) || (cx == 2 && dx == 2)) continue;
                sum += w_in[(o * 25 + 24) * 9 + dy * 3 + dx];
            }
        }
        sfold[(size_t)n * 576 + cs * 64 + o] = a * sum;
    }
}

// ----------------------------------------------------------------------------
// weight prep (layers 1..5): OIHW fp32 -> f16 B-fragment layout
// ----------------------------------------------------------------------------
__global__ __launch_bounds__(256)
void wprep_kernel(const float* __restrict__ w1s, const float* __restrict__ w2s,
                  const float* __restrict__ w_out, uint32_t* __restrict__ wfrag)
{
    const int layer = blockIdx.x + 1;   // 1..4 hidden, 5 out
    const int tid = threadIdx.x;

    const float* w;
    int cin, cout, woff, nwords, chunks, ntb;
    if (layer <= 4) {
        const int blk = (layer - 1) >> 1;
        w = ((layer - 1) & 1) ? (w2s + (size_t)blk * 64 * 64 * 9)
                              : (w1s + (size_t)blk * 64 * 64 * 9);
        cin = 64; cout = 64; woff = WOFF_HID0 + (layer - 1) * 18432; nwords = 18432; chunks = 36; ntb = 4;
    } else {
        w = w_out; cin = 64; cout = 9;  woff = WOFF_OUT; nwords = 4608; chunks = 36; ntb = 2;
    }

    for (int i = tid; i < nwords; i += 256) wfrag[woff + i] = 0u;
    __syncthreads();

    __half* wh = (__half*)(wfrag);
    const int wtot = cout * cin * 9;
    for (int i = tid; i < wtot; i += 256) {
        const int tap = i % 9;
        const int ci  = (i / 9) % cin;
        const int co  = i / (9 * cin);
        const int cg  = ci >> 5;
        const int kin = ci & 31;
        const int g2  = kin >> 4;
        const int k16 = kin & 15;
        const int chunk = (cg * 9 + tap) * 2 + g2;
        const int hi  = k16 >> 3;
        const int rem = k16 & 7;
        const int tt  = rem >> 1;
        const int hf  = rem & 1;
        const int lane = (co & 7) * 4 + tt;
        int word;
        if (ntb == 4) {
            const int nhalf = co >> 5;
            const int nt4   = (co >> 3) & 3;
            word = woff + nhalf * chunks * 256 + (chunk * 4 + nt4) * 64 + lane * 2 + hi;
        } else {
            const int nt = co >> 3;
            word = woff + (chunk * 2 + nt) * 64 + lane * 2 + hi;
        }
        wh[word * 2 + hf] = __float2half(w[i]);
    }
}

// ----------------------------------------------------------------------------
// conv_in (fused prep, MERGED halves): one CTA per image; X staged once per
// tile; both 32-channel output halves computed sequentially from the same X.
// ----------------------------------------------------------------------------
__global__ __launch_bounds__(256, 2)
void conv_in16(const __half* __restrict__ kf, const uint32_t* __restrict__ wfold,
               const float* __restrict__ sfold, const float* __restrict__ bias,
               __half* __restrict__ out, const int* __restrict__ idx)
{
    constexpr int NTB = 4;
    constexpr int BW  = 2 * 9 * NTB * 64;   // both halves: 4608 words
    extern __shared__ uint32_t smem[];
    uint32_t* b_s = smem;
    uint32_t* X_s = smem + BW;              // 2 buffers * 4896 words

    const int tid   = threadIdx.x;
    const int wid   = tid >> 5;
    const int lane  = tid & 31;
    const int n     = blockIdx.x;
    const int tx    = lane >> 2;
    const int kq2   = (lane & 3) * 2;

    int t0, t1; float a, araw;
    seg_params(idx, n >> 7, n & 127, t0, t1, a, araw);
    const int fb = n >> 7;
    const char* kf0 = (const char*)(kf + ((size_t)(fb * 128 + t0)) * HW * 8);
    const char* kf1 = (const char*)(kf + ((size_t)(fb * 128 + t1)) * HW * 8);
    const char* kfp = (tid & 1) ? kf1 : kf0;

    const uint32_t bs_u = smem_u32(b_s);
    const uint32_t xs_u = smem_u32(X_s);

    // both B half-sets (joins cp group 0)
    const uint32_t* wsrc = wfold + (size_t)n * 4608;
    for (int i = tid; i < BW / 4; i += 256)
        cp_async16(bs_u + i * 16, wsrc + i * 4, 16);

    uint32_t s_dst[5];
#pragma unroll
    for (int q = 0; q < 5; q++) {
        const int i = tid + q * 256;
        const int px = i >> 1, part = i & 1;
        s_dst[q] = (uint32_t)(px * 32 + part * 16);
    }

    auto stage_tile = [&](int tile) {
#pragma unroll
        for (int q = 0; q < 5; q++) {
            const int i = tid + q * 256;
            if (q < 4 || tid < 200) {
                const int px = i >> 1;
                const int rr = px / 34;
                const int gx = px - rr * 34 - 1;
                const int gy = tile * 16 - 1 + rr;
                const bool ok = (gx >= 0) && (gx < 32) && (gy >= 0) && (gy < 32)
                                && (i < 1224);
                const int pix = ok ? (gy * 32 + gx) : 0;
                cp_async16(xs_u + tile * 19584 + s_dst[q], kfp + (size_t)pix * 16,
                           ok ? 16u : 0u);
            }
        }
        cp_commit();
    };

    stage_tile(0);
    stage_tile(1);

    const float* Sp = sfold + (size_t)n * 576;

#pragma unroll 1
    for (int tile = 0; tile < 2; tile++) {
        if (tile == 0) cp_wait1(); else cp_wait0();
        __syncthreads();
        const uint32_t* Xb = X_s + tile * 4896;

#pragma unroll 1
        for (int nh = 0; nh < 2; nh++) {
            const int ch0 = nh * 32;
            float bv[NTB][2];
#pragma unroll
            for (int nt = 0; nt < NTB; nt++) {
                bv[nt][0] = bias[ch0 + nt * 8 + kq2];
                bv[nt][1] = bias[ch0 + nt * 8 + kq2 + 1];
            }

            float d[4][NTB][4];
#pragma unroll
            for (int f = 0; f < 4; f++)
#pragma unroll
                for (int nt = 0; nt < NTB; nt++)
#pragma unroll
                    for (int q = 0; q < 4; q++) d[f][nt][q] = 0.f;

#pragma unroll
            for (int tap = 0; tap < 9; tap++) {
                const int dy = tap / 3, dx = tap - 3 * (tap / 3);
                const uint32_t* A = Xb + ((2 * wid + dy) * 34 + tx + dx) * 8 + kq2;
                const uint2 u0 = *(const uint2*)(A);
                const uint2 u1 = *(const uint2*)(A + 64);
                const uint2 u2 = *(const uint2*)(A + 128);
                const uint2 u3 = *(const uint2*)(A + 192);
                const uint2 u4 = *(const uint2*)(A + 272);
                const uint2 u5 = *(const uint2*)(A + 336);
                const uint2 u6 = *(const uint2*)(A + 400);
                const uint2 u7 = *(const uint2*)(A + 464);
                const uint32_t* bp = b_s + (size_t)(nh * 9 + tap) * NTB * 64 + lane * 2;
#pragma unroll
                for (int nt = 0; nt < NTB; nt++) {
                    const uint2 b = *(const uint2*)(bp + nt * 64);
                    mma_f16(d[0][nt], u0.x, u1.x, u0.y, u1.y, b.x, b.y);
                    mma_f16(d[1][nt], u2.x, u3.x, u2.y, u3.y, b.x, b.y);
                    mma_f16(d[2][nt], u4.x, u5.x, u4.y, u5.y, b.x, b.y);
                    mma_f16(d[3][nt], u6.x, u7.x, u6.y, u7.y, b.x, b.y);
                }
            }

            // epilogue: alpha border correction + bias + SiLU, permuted fp16
#pragma unroll
            for (int f = 0; f < 4; f++) {
                const int gy  = tile * 16 + 2 * wid + (f >> 1);
                const int gx0 = ((f & 1) << 4) + tx;
                const int gx1 = gx0 + 8;
                const int cy  = (gy == 0) ? 0 : ((gy == 31) ? 2 : 1);
                const int cx0 = (gx0 == 0) ? 0 : ((gx0 == 31) ? 2 : 1);
                const int cx1 = (gx1 == 31) ? 2 : 1;
                const int base0 = (cy * 3 + cx0) * 64;
                const int base1 = (cy * 3 + cx1) * 64;
                const size_t gp0 = (size_t)n * HW + gy * 32 + gx0;
                const size_t gp1 = gp0 + 8;
#pragma unroll
                for (int nt = 0; nt < NTB; nt++) {
                    const int c = ch0 + nt * 8 + kq2;
                    float v00 = d[f][nt][0] + bv[nt][0] + Sp[base0 + c];
                    float v01 = d[f][nt][1] + bv[nt][1] + Sp[base0 + c + 1];
                    float v10 = d[f][nt][2] + bv[nt][0] + Sp[base1 + c];
                    float v11 = d[f][nt][3] + bv[nt][1] + Sp[base1 + c + 1];
                    v00 = __fdividef(v00, 1.f + __expf(-v00));
                    v01 = __fdividef(v01, 1.f + __expf(-v01));
                    v10 = __fdividef(v10, 1.f + __expf(-v10));
                    v11 = __fdividef(v11, 1.f + __expf(-v11));
                    const int g16 = c >> 4;
                    const int cl  = c & 15;
                    const int jl  = (((cl >> 3) & 1) << 1) | (((cl >> 1) & 3) << 2);
                    __half2* oh = (__half2*)out;
                    oh[(gp0 * 64 + g16 * 16 + jl) >> 1] = __floats2half2_rn(v00, v01);
                    oh[(gp1 * 64 + g16 * 16 + jl) >> 1] = __floats2half2_rn(v10, v11);
                }
            }
        }
    }
}

// ----------------------------------------------------------------------------
// hidden/out conv (R11 proven config): mma.sync m16n8k16, M64xN=NTB*8 per
// warp, 3-buffer slab pipeline. FINAL fuses z_hat/conf finalize.
// ----------------------------------------------------------------------------
template<int NTB, bool SILU, bool RESID, bool FINAL>
__global__ __launch_bounds__(256, 2)
void conv_mma(const void* __restrict__ in_v, const uint32_t* __restrict__ wfrag,
              const float* __restrict__ bias, void* __restrict__ out_v,
              const void* __restrict__ resid_v,
              const float* __restrict__ latents, const int* __restrict__ idx)
{
    constexpr int CIN    = 64;
    constexpr int CHUNKS = 36;
    constexpr int BW     = CHUNKS * NTB * 64;
    constexpr int SLABS  = 4;
    constexpr int NSTAGE = 8;
    constexpr bool F16OUT = (NTB == 4);

    extern __shared__ uint32_t smem[];
    uint32_t* b_s = smem;
    uint32_t* X_s = smem + BW;

    const int tid   = threadIdx.x;
    const int wid   = tid >> 5;
    const int lane  = tid & 31;
    const int n     = blockIdx.x;
    const int nhalf = blockIdx.y;
    const int tx    = lane >> 2;
    const int kq2   = (lane & 3) * 2;
    const int ch0   = F16OUT ? nhalf * 32 : 0;

    const uint32_t bs_u = smem_u32(b_s);
    const uint32_t xs_u = smem_u32(X_s);
    const char* in_b = (const char*)in_v + (size_t)n * HW * CIN * 2;

    float fs_a = 0.f, fs_s = 0.f;
    bool  fs_int = false;
    const float* L0f = nullptr;
    const float* L1f = nullptr;
    if constexpr (FINAL) {
        int t0, t1; float araw;
        seg_params(idx, n >> 7, n & 127, t0, t1, fs_a, araw);
        fs_s   = fs_a * (1.f - fs_a);
        fs_int = (araw > 0.f) && (araw < 1.f);
        L0f = latents + ((size_t)((n >> 7) * 128 + t0)) * 8 * HW;
        L1f = latents + ((size_t)((n >> 7) * 128 + t1)) * 8 * HW;
    }

    const uint32_t* wsrc = wfrag + (size_t)nhalf * CHUNKS * NTB * 64;
    for (int i = tid; i < BW / 4; i += 256)
        cp_async16(bs_u + i * 16, wsrc + i * 4, 16);

    uint32_t s_dst[5];
#pragma unroll
    for (int q = 0; q < 5; q++) {
        const int i = tid + q * 256;
        const int px = i >> 1, part = i & 1;
        s_dst[q] = (uint32_t)(px * 32 + part * 16);
    }
    int s_src[5];
    uint32_t okb = 0;
    int cached_tile = -1;

    auto stage_slab = [&](int s) {
        const int tile = s / SLABS;
        const int k    = s - tile * SLABS;
        if (tile != cached_tile) {
            cached_tile = tile;
            okb = 0;
#pragma unroll
            for (int q = 0; q < 5; q++) {
                const int i = tid + q * 256;
                const int px = i >> 1, part = i & 1;
                const int rr = px / 34;
                const int gx = px - rr * 34 - 1;
                const int gy = tile * 16 - 1 + rr;
                const bool ok = (gx >= 0) && (gx < 32) && (gy >= 0) && (gy < 32)
                                && (i < 1224);
                const int pix = ok ? (gy * 32 + gx) : 0;
                s_src[q] = pix * CIN * 2 + part * 16;
                okb |= (ok ? 1u : 0u) << q;
            }
        }
        const uint32_t xoff = (uint32_t)((s % 3) * 19584);
#pragma unroll
        for (int q = 0; q < 5; q++) {
            if (q < 4 || tid < 200)
                cp_async16(xs_u + xoff + s_dst[q], in_b + s_src[q] + k * 32,
                           ((okb >> q) & 1) ? 16u : 0u);
        }
        cp_commit();
    };

    stage_slab(0);
    stage_slab(1);

    float bv[NTB][2];
#pragma unroll
    for (int nt = 0; nt < NTB; nt++) {
        const int bi = ch0 + nt * 8 + kq2;
        bv[nt][0] = (F16OUT || bi     < 9) ? bias[bi]     : 0.f;
        bv[nt][1] = (F16OUT || bi + 1 < 9) ? bias[bi + 1] : 0.f;
    }

    float d[4][NTB][4];

#pragma unroll 1
    for (int s = 0; s < NSTAGE; s++) {
        const int tile = s / SLABS;
        const int k    = s - tile * SLABS;

        if (s + 1 < NSTAGE) cp_wait1(); else cp_wait0();
        __syncthreads();
        if (s + 2 < NSTAGE) stage_slab(s + 2);

        if (k == 0) {
#pragma unroll
            for (int f = 0; f < 4; f++)
#pragma unroll
                for (int nt = 0; nt < NTB; nt++)
#pragma unroll
                    for (int q = 0; q < 4; q++) d[f][nt][q] = 0.f;
        }

        const uint32_t* Xb = X_s + (s % 3) * 4896;
        const int cbase = (k >> 1) * 18 + (k & 1);

#pragma unroll
        for (int tap = 0; tap < 9; tap++) {
            const int dy = tap / 3, dx = tap - 3 * (tap / 3);
            const uint32_t* A = Xb + ((2 * wid + dy) * 34 + tx + dx) * 8 + kq2;
            const uint2 u0 = *(const uint2*)(A);
            const uint2 u1 = *(const uint2*)(A + 64);
            const uint2 u2 = *(const uint2*)(A + 128);
            const uint2 u3 = *(const uint2*)(A + 192);
            const uint2 u4 = *(const uint2*)(A + 272);
            const uint2 u5 = *(const uint2*)(A + 336);
            const uint2 u6 = *(const uint2*)(A + 400);
            const uint2 u7 = *(const uint2*)(A + 464);
            const uint32_t* bp = b_s + (size_t)(cbase + tap * 2) * NTB * 64 + lane * 2;
#pragma unroll
            for (int nt = 0; nt < NTB; nt++) {
                const uint2 b = *(const uint2*)(bp + nt * 64);
                mma_f16(d[0][nt], u0.x, u1.x, u0.y, u1.y, b.x, b.y);
                mma_f16(d[1][nt], u2.x, u3.x, u2.y, u3.y, b.x, b.y);
                mma_f16(d[2][nt], u4.x, u5.x, u4.y, u5.y, b.x, b.y);
                mma_f16(d[3][nt], u6.x, u7.x, u6.y, u7.y, b.x, b.y);
            }
        }

        if (k == SLABS - 1) {
#pragma unroll
            for (int f = 0; f < 4; f++) {
                const int gy = tile * 16 + 2 * wid + (f >> 1);
                const int gx = ((f & 1) << 4) + tx;
                const int p0i = gy * 32 + gx;
                const size_t gp0 = (size_t)n * HW + p0i;
                const size_t gp1 = gp0 + 8;

                if constexpr (FINAL) {
                    float* outp = (float*)out_v;
#pragma unroll
                    for (int e = 0; e < 2; e++) {
                        const int c = kq2 + e;
                        const float r0 = d[f][0][e]     + bv[0][e];
                        const float r1 = d[f][0][2 + e] + bv[0][e];
                        const float zb0 = (1.f - fs_a) * L0f[c * HW + p0i]
                                        + fs_a * L1f[c * HW + p0i];
                        const float zb1 = (1.f - fs_a) * L0f[c * HW + p0i + 8]
                                        + fs_a * L1f[c * HW + p0i + 8];
                        outp[((size_t)n * 8 + c) * HW + p0i]     = zb0 + fs_s * r0;
                        outp[((size_t)n * 8 + c) * HW + p0i + 8] = zb1 + fs_s * r1;
                    }
                    if (kq2 == 0) {
                        const float l0 = d[f][1][0] + bv[1][0];
                        const float l1 = d[f][1][2] + bv[1][0];
                        float c0 = 1.f, c1 = 1.f;
                        if (fs_int) {
                            c0 = 1.f - __fdividef(1.f, 1.f + __expf(-l0));
                            c1 = 1.f - __fdividef(1.f, 1.f + __expf(-l1));
                            c0 = fminf(fmaxf(c0, 0.f), 1.f);
                            c1 = fminf(fmaxf(c1, 0.f), 1.f);
                        }
                        float* cf = outp + (size_t)NIMG * 8 * HW + (size_t)n * HW;
                        cf[p0i]     = c0;
                        cf[p0i + 8] = c1;
                    }
                } else {
#pragma unroll
                    for (int nt = 0; nt < NTB; nt++) {
                        const int c = ch0 + nt * 8 + kq2;
                        float v00 = d[f][nt][0] + bv[nt][0];
                        float v01 = d[f][nt][1] + bv[nt][1];
                        float v10 = d[f][nt][2] + bv[nt][0];
                        float v11 = d[f][nt][3] + bv[nt][1];
                        if (SILU) {
                            v00 = __fdividef(v00, 1.f + __expf(-v00));
                            v01 = __fdividef(v01, 1.f + __expf(-v01));
                            v10 = __fdividef(v10, 1.f + __expf(-v10));
                            v11 = __fdividef(v11, 1.f + __expf(-v11));
                        }
                        const int g16 = c >> 4;
                        const int cl  = c & 15;
                        const int jl  = (((cl >> 3) & 1) << 1) | (((cl >> 1) & 3) << 2);
                        const size_t h0 = gp0 * 64 + g16 * 16 + jl;
                        const size_t h1 = gp1 * 64 + g16 * 16 + jl;
                        if (RESID) {
                            const __half2* rh = (const __half2*)resid_v;
                            const float2 r0 = __half22float2(rh[h0 >> 1]);
                            const float2 r1 = __half22float2(rh[h1 >> 1]);
                            v00 += r0.x; v01 += r0.y; v10 += r1.x; v11 += r1.y;
                        }
                        __half2* oh = (__half2*)out_v;
                        oh[h0 >> 1] = __floats2half2_rn(v00, v01);
                        oh[h1 >> 1] = __floats2half2_rn(v10, v11);
                    }
                }
            }
        }
    }
}

// ----------------------------------------------------------------------------
// launch
// ----------------------------------------------------------------------------
extern "C" void kernel_launch(void* const* d_in, const int* in_sizes, int n_in,
                              void* d_out, int out_size)
{
    const float* latents = (const float*)d_in[0];
    const int*   idx     = (const int*)d_in[1];
    const float* w_in    = (const float*)d_in[2];
    const float* b_in    = (const float*)d_in[3];
    const float* w1s     = (const float*)d_in[4];
    const float* b1s     = (const float*)d_in[5];
    const float* w2s     = (const float*)d_in[6];
    const float* b2s     = (const float*)d_in[7];
    const float* w_out   = (const float*)d_in[8];
    const float* b_out   = (const float*)d_in[9];
    float* outp = (float*)d_out;

    __half *kf, *h, *tmp;
    uint32_t *wfrag, *wfold;
    float* sfold;
    cudaGetSymbolAddress((void**)&kf,    g_kf16);
    cudaGetSymbolAddress((void**)&h,     g_h);
    cudaGetSymbolAddress((void**)&tmp,   g_tmp);
    cudaGetSymbolAddress((void**)&wfrag, g_wfrag);
    cudaGetSymbolAddress((void**)&wfold, g_wfold);
    cudaGetSymbolAddress((void**)&sfold, g_sfold);

    constexpr int SM_IN16 = ( 4608 + 2 * 4896) * 4;   // 57,600
    constexpr int SM_HID  = ( 9216 + 3 * 4896) * 4;   // 95,616
    constexpr int SM_OUT  = ( 4608 + 3 * 4896) * 4;   // 77,184

    cudaFuncSetAttribute(conv_in16,
                         cudaFuncAttributeMaxDynamicSharedMemorySize, SM_IN16);
    cudaFuncSetAttribute(conv_mma<4, true,  false, false>,
                         cudaFuncAttributeMaxDynamicSharedMemorySize, SM_HID);
    cudaFuncSetAttribute(conv_mma<4, false, true,  false>,
                         cudaFuncAttributeMaxDynamicSharedMemorySize, SM_HID);
    cudaFuncSetAttribute(conv_mma<2, false, false, true>,
                         cudaFuncAttributeMaxDynamicSharedMemorySize, SM_OUT);

    kf_kernel<<<NIMG, 256>>>(latents, kf);
    fold_kernel<<<NIMG, 256>>>(w_in, idx, wfold, sfold);
    wprep_kernel<<<5, 256>>>(w1s, w2s, w_out, wfrag);

    // conv_in (fused prep, merged halves): z0|z1 16ch -> 64, SiLU
    conv_in16<<<dim3(NIMG, 1), 256, SM_IN16>>>(kf, wfold, sfold, b_in, h, idx);

    for (int blk = 0; blk < 2; blk++) {
        const float* b1 = b1s + blk * 64;
        const float* b2 = b2s + blk * 64;
        conv_mma<4, true, false, false><<<dim3(NIMG, 2), 256, SM_HID>>>(
            h, wfrag + WOFF_HID0 + (2 * blk) * 18432, b1, tmp, nullptr, nullptr, nullptr);
        conv_mma<4, false, true, false><<<dim3(NIMG, 2), 256, SM_HID>>>(
            tmp, wfrag + WOFF_HID0 + (2 * blk + 1) * 18432, b2, h, h, nullptr, nullptr);
    }

    // conv_out: 64 -> 9, fused finalize -> d_out (z_hat NCHW + conf)
    conv_mma<2, false, false, true><<<dim3(NIMG, 1), 256, SM_OUT>>>(
        h, wfrag + WOFF_OUT, b_out, outp, nullptr, latents, idx);
}

// round 14
// speedup vs baseline: 1.0237x; 1.0087x over previous
#include <cuda_runtime.h>
#include <cuda_fp16.h>
#include <cstdint>
#include <cstring>

#define NIMG 512
#define HW   1024

// ----------------------------------------------------------------------------
// scratch (device globals; no runtime allocation)
// ----------------------------------------------------------------------------
__device__ __half    g_kf16[(size_t)NIMG * HW * 8];    // latents fp16 NHWC8
__device__ __half    g_h[(size_t)NIMG * HW * 64];      // fp16 NHWC64 (permuted)
__device__ __half    g_tmp[(size_t)NIMG * HW * 64];    // fp16 NHWC64 (permuted)
__device__ uint32_t  g_wfrag[131072];                  // layers 1-5 B frags
__device__ uint32_t  g_wfold[(size_t)NIMG * 4608];     // per-image conv_in B frags
__device__ float     g_sfold[(size_t)NIMG * 576];      // per-image alpha border terms

#define WOFF_HID0 9216
#define WOFF_OUT  (9216 + 4 * 18432)   // 82944

__device__ __forceinline__ void mma_f16(float d[4], uint32_t a0, uint32_t a1,
                                        uint32_t a2, uint32_t a3,
                                        uint32_t b0, uint32_t b1) {
    asm volatile(
        "mma.sync.aligned.m16n8k16.row.col.f32.f16.f16.f32 "
        "{%0,%1,%2,%3}, {%4,%5,%6,%7}, {%8,%9}, {%0,%1,%2,%3};"
        : "+f"(d[0]), "+f"(d[1]), "+f"(d[2]), "+f"(d[3])
        : "r"(a0), "r"(a1), "r"(a2), "r"(a3), "r"(b0), "r"(b1));
}

__device__ __forceinline__ void cp_async16(uint32_t dst, const void* src, uint32_t srcsize) {
    asm volatile("cp.async.ca.shared.global [%0], [%1], 16, %2;"
                 :: "r"(dst), "l"(src), "r"(srcsize) : "memory");
}
__device__ __forceinline__ void cp_commit() {
    asm volatile("cp.async.commit_group;" ::: "memory");
}
__device__ __forceinline__ void cp_wait0() {
    asm volatile("cp.async.wait_group 0;" ::: "memory");
}
__device__ __forceinline__ void cp_wait1() {
    asm volatile("cp.async.wait_group 1;" ::: "memory");
}
__device__ __forceinline__ uint32_t smem_u32(const void* p) {
    uint32_t a;
    asm("{ .reg .u64 t; cvta.to.shared.u64 t, %1; cvt.u32.u64 %0, t; }"
        : "=r"(a) : "l"(p));
    return a;
}
__device__ __forceinline__ uint32_t h2u(__half2 h) {
    uint32_t u; memcpy(&u, &h, 4); return u;
}

// sort idx + derive segment for image (b,t)
__device__ __forceinline__ void seg_params(const int* __restrict__ idx, int b, int t,
                                           int& t0, int& t1, float& a, float& araw) {
    int v[9];
#pragma unroll
    for (int k = 0; k < 9; k++) v[k] = idx[b * 9 + k];
#pragma unroll
    for (int i = 1; i < 9; i++) {
        int key = v[i]; int j = i - 1;
        while (j >= 0 && v[j] > key) { v[j + 1] = v[j]; j--; }
        v[j + 1] = key;
    }
    int cnt = 0;
#pragma unroll
    for (int k = 0; k < 9; k++) cnt += (v[k] <= t);
    int seg = min(max(cnt - 1, 0), 7);
    t0 = v[seg]; t1 = v[seg + 1];
    araw = (float)(t - t0) / (float)max(t1 - t0, 1);
    a = fminf(fmaxf(araw, 0.f), 1.f);
}

// ----------------------------------------------------------------------------
// kf convert: all latent frames fp32 NCHW -> fp16 per-pixel 8ch
// ----------------------------------------------------------------------------
__global__ __launch_bounds__(256)
void kf_kernel(const float* __restrict__ latents, __half* __restrict__ kf)
{
    const int fr = blockIdx.x;
    const int tid = threadIdx.x;
    const float* L = latents + (size_t)fr * 8 * HW;
#pragma unroll
    for (int j = 0; j < 4; j++) {
        const int p = tid + j * 256;
        uint32_t w[4];
#pragma unroll
        for (int q = 0; q < 4; q++)
            w[q] = h2u(__floats2half2_rn(L[(2*q) * HW + p], L[(2*q+1) * HW + p]));
        *(uint4*)(kf + ((size_t)fr * HW + p) * 8) = make_uint4(w[0], w[1], w[2], w[3]);
    }
}

// ----------------------------------------------------------------------------
// fold conv_in weights per image:
//   U = (1-a)W0 + W1 on z0 slots, V = a W0 + W2 on z1 slots, alpha border S.
// ----------------------------------------------------------------------------
__global__ __launch_bounds__(256)
void fold_kernel(const float* __restrict__ w_in, const int* __restrict__ idx,
                 uint32_t* __restrict__ wfold, float* __restrict__ sfold)
{
    const int n = blockIdx.x;
    const int tid = threadIdx.x;
    int t0, t1; float a, araw;
    seg_params(idx, n >> 7, n & 127, t0, t1, a, araw);

    __half* wh = (__half*)(wfold + (size_t)n * 4608);
    for (int i = tid; i < 4608; i += 256) {
        const int o   = i / 72;
        const int r   = i % 72;
        const int tap = r / 8;
        const int ci  = r % 8;
        const float W0 = w_in[(o * 25 + ci) * 9 + tap];
        const float W1 = w_in[(o * 25 + 8 + ci) * 9 + tap];
        const float W2 = w_in[(o * 25 + 16 + ci) * 9 + tap];
        const float U  = (1.f - a) * W0 + W1;
        const float V  = a * W0 + W2;
        const int kz0 = 2 * (ci >> 2) + 8 * ((ci >> 1) & 1) + (ci & 1);
#pragma unroll
        for (int h = 0; h < 2; h++) {
            const int k  = kz0 + 4 * h;
            const int hi = k >> 3, rem = k & 7, tt = rem >> 1, hf = rem & 1;
            const int lane = (o & 7) * 4 + tt;
            const int word = (o >> 5) * 2304 + (tap * 4 + ((o >> 3) & 3)) * 64 + lane * 2 + hi;
            wh[word * 2 + hf] = __float2half(h ? V : U);
        }
    }
    for (int i = tid; i < 576; i += 256) {
        const int o  = i / 9;
        const int cs = i % 9;
        const int cy = cs / 3, cx = cs % 3;
        float sum = 0.f;
#pragma unroll
        for (int dy = 0; dy < 3; dy++) {
            if ((cy == 0 && dy == 0) || (cy == 2 && dy == 2)) continue;
#pragma unroll
            for (int dx = 0; dx < 3; dx++) {
                if ((cx == 0 && dx == 0) || (cx == 2 && dx == 2)) continue;
                sum += w_in[(o * 25 + 24) * 9 + dy * 3 + dx];
            }
        }
        sfold[(size_t)n * 576 + cs * 64 + o] = a * sum;
    }
}

// ----------------------------------------------------------------------------
// weight prep (layers 1..5): OIHW fp32 -> f16 B-fragment layout
// ----------------------------------------------------------------------------
__global__ __launch_bounds__(256)
void wprep_kernel(const float* __restrict__ w1s, const float* __restrict__ w2s,
                  const float* __restrict__ w_out, uint32_t* __restrict__ wfrag)
{
    const int layer = blockIdx.x + 1;   // 1..4 hidden, 5 out
    const int tid = threadIdx.x;

    const float* w;
    int cin, cout, woff, nwords, chunks, ntb;
    if (layer <= 4) {
        const int blk = (layer - 1) >> 1;
        w = ((layer - 1) & 1) ? (w2s + (size_t)blk * 64 * 64 * 9)
                              : (w1s + (size_t)blk * 64 * 64 * 9);
        cin = 64; cout = 64; woff = WOFF_HID0 + (layer - 1) * 18432; nwords = 18432; chunks = 36; ntb = 4;
    } else {
        w = w_out; cin = 64; cout = 9;  woff = WOFF_OUT; nwords = 4608; chunks = 36; ntb = 2;
    }

    for (int i = tid; i < nwords; i += 256) wfrag[woff + i] = 0u;
    __syncthreads();

    __half* wh = (__half*)(wfrag);
    const int wtot = cout * cin * 9;
    for (int i = tid; i < wtot; i += 256) {
        const int tap = i % 9;
        const int ci  = (i / 9) % cin;
        const int co  = i / (9 * cin);
        const int cg  = ci >> 5;
        const int kin = ci & 31;
        const int g2  = kin >> 4;
        const int k16 = kin & 15;
        const int chunk = (cg * 9 + tap) * 2 + g2;
        const int hi  = k16 >> 3;
        const int rem = k16 & 7;
        const int tt  = rem >> 1;
        const int hf  = rem & 1;
        const int lane = (co & 7) * 4 + tt;
        int word;
        if (ntb == 4) {
            const int nhalf = co >> 5;
            const int nt4   = (co >> 3) & 3;
            word = woff + nhalf * chunks * 256 + (chunk * 4 + nt4) * 64 + lane * 2 + hi;
        } else {
            const int nt = co >> 3;
            word = woff + (chunk * 2 + nt) * 64 + lane * 2 + hi;
        }
        wh[word * 2 + hf] = __float2half(w[i]);
    }
}

// ----------------------------------------------------------------------------
// conv_in (fused prep, R11 split version): 16 real channels (z0|z1 from kf16),
// per-image folded weights, alpha border correction, SiLU. Grid (512, 2).
// ----------------------------------------------------------------------------
__global__ __launch_bounds__(256, 2)
void conv_in16(const __half* __restrict__ kf, const uint32_t* __restrict__ wfold,
               const float* __restrict__ sfold, const float* __restrict__ bias,
               __half* __restrict__ out, const int* __restrict__ idx)
{
    constexpr int NTB = 4;
    constexpr int BW  = 9 * NTB * 64;   // 2304 words
    extern __shared__ uint32_t smem[];
    uint32_t* b_s = smem;
    uint32_t* X_s = smem + BW;

    const int tid   = threadIdx.x;
    const int wid   = tid >> 5;
    const int lane  = tid & 31;
    const int n     = blockIdx.x;
    const int nhalf = blockIdx.y;
    const int tx    = lane >> 2;
    const int kq2   = (lane & 3) * 2;
    const int ch0   = nhalf * 32;

    int t0, t1; float a, araw;
    seg_params(idx, n >> 7, n & 127, t0, t1, a, araw);
    const int fb = n >> 7;
    const char* kf0 = (const char*)(kf + ((size_t)(fb * 128 + t0)) * HW * 8);
    const char* kf1 = (const char*)(kf + ((size_t)(fb * 128 + t1)) * HW * 8);
    const char* kfp = (tid & 1) ? kf1 : kf0;

    const uint32_t bs_u = smem_u32(b_s);
    const uint32_t xs_u = smem_u32(X_s);

    const uint32_t* wsrc = wfold + (size_t)n * 4608 + nhalf * 2304;
    for (int i = tid; i < BW / 4; i += 256)
        cp_async16(bs_u + i * 16, wsrc + i * 4, 16);

    uint32_t s_dst[5];
#pragma unroll
    for (int q = 0; q < 5; q++) {
        const int i = tid + q * 256;
        const int px = i >> 1, part = i & 1;
        s_dst[q] = (uint32_t)(px * 32 + part * 16);
    }

    auto stage_tile = [&](int tile) {
#pragma unroll
        for (int q = 0; q < 5; q++) {
            const int i = tid + q * 256;
            if (q < 4 || tid < 200) {
                const int px = i >> 1;
                const int rr = px / 34;
                const int gx = px - rr * 34 - 1;
                const int gy = tile * 16 - 1 + rr;
                const bool ok = (gx >= 0) && (gx < 32) && (gy >= 0) && (gy < 32)
                                && (i < 1224);
                const int pix = ok ? (gy * 32 + gx) : 0;
                cp_async16(xs_u + tile * 19584 + s_dst[q], kfp + (size_t)pix * 16,
                           ok ? 16u : 0u);
            }
        }
        cp_commit();
    };

    stage_tile(0);
    stage_tile(1);

    float bv[NTB][2];
#pragma unroll
    for (int nt = 0; nt < NTB; nt++) {
        bv[nt][0] = bias[ch0 + nt * 8 + kq2];
        bv[nt][1] = bias[ch0 + nt * 8 + kq2 + 1];
    }
    const float* Sp = sfold + (size_t)n * 576;

#pragma unroll 1
    for (int tile = 0; tile < 2; tile++) {
        if (tile == 0) cp_wait1(); else cp_wait0();
        __syncthreads();

        float d[4][NTB][4];
#pragma unroll
        for (int f = 0; f < 4; f++)
#pragma unroll
            for (int nt = 0; nt < NTB; nt++)
#pragma unroll
                for (int q = 0; q < 4; q++) d[f][nt][q] = 0.f;

        const uint32_t* Xb = X_s + tile * 4896;

#pragma unroll
        for (int tap = 0; tap < 9; tap++) {
            const int dy = tap / 3, dx = tap - 3 * (tap / 3);
            const uint32_t* A = Xb + ((2 * wid + dy) * 34 + tx + dx) * 8 + kq2;
            const uint2 u0 = *(const uint2*)(A);
            const uint2 u1 = *(const uint2*)(A + 64);
            const uint2 u2 = *(const uint2*)(A + 128);
            const uint2 u3 = *(const uint2*)(A + 192);
            const uint2 u4 = *(const uint2*)(A + 272);
            const uint2 u5 = *(const uint2*)(A + 336);
            const uint2 u6 = *(const uint2*)(A + 400);
            const uint2 u7 = *(const uint2*)(A + 464);
            const uint32_t* bp = b_s + (size_t)tap * NTB * 64 + lane * 2;
#pragma unroll
            for (int nt = 0; nt < NTB; nt++) {
                const uint2 b = *(const uint2*)(bp + nt * 64);
                mma_f16(d[0][nt], u0.x, u1.x, u0.y, u1.y, b.x, b.y);
                mma_f16(d[1][nt], u2.x, u3.x, u2.y, u3.y, b.x, b.y);
                mma_f16(d[2][nt], u4.x, u5.x, u4.y, u5.y, b.x, b.y);
                mma_f16(d[3][nt], u6.x, u7.x, u6.y, u7.y, b.x, b.y);
            }
        }

#pragma unroll
        for (int f = 0; f < 4; f++) {
            const int gy  = tile * 16 + 2 * wid + (f >> 1);
            const int gx0 = ((f & 1) << 4) + tx;
            const int gx1 = gx0 + 8;
            const int cy  = (gy == 0) ? 0 : ((gy == 31) ? 2 : 1);
            const int cx0 = (gx0 == 0) ? 0 : ((gx0 == 31) ? 2 : 1);
            const int cx1 = (gx1 == 31) ? 2 : 1;
            const int base0 = (cy * 3 + cx0) * 64;
            const int base1 = (cy * 3 + cx1) * 64;
            const size_t gp0 = (size_t)n * HW + gy * 32 + gx0;
            const size_t gp1 = gp0 + 8;
#pragma unroll
            for (int nt = 0; nt < NTB; nt++) {
                const int c = ch0 + nt * 8 + kq2;
                float v00 = d[f][nt][0] + bv[nt][0] + Sp[base0 + c];
                float v01 = d[f][nt][1] + bv[nt][1] + Sp[base0 + c + 1];
                float v10 = d[f][nt][2] + bv[nt][0] + Sp[base1 + c];
                float v11 = d[f][nt][3] + bv[nt][1] + Sp[base1 + c + 1];
                v00 = __fdividef(v00, 1.f + __expf(-v00));
                v01 = __fdividef(v01, 1.f + __expf(-v01));
                v10 = __fdividef(v10, 1.f + __expf(-v10));
                v11 = __fdividef(v11, 1.f + __expf(-v11));
                const int g16 = c >> 4;
                const int cl  = c & 15;
                const int jl  = (((cl >> 3) & 1) << 1) | (((cl >> 1) & 3) << 2);
                __half2* oh = (__half2*)out;
                oh[(gp0 * 64 + g16 * 16 + jl) >> 1] = __floats2half2_rn(v00, v01);
                oh[(gp1 * 64 + g16 * 16 + jl) >> 1] = __floats2half2_rn(v10, v11);
            }
        }
        if (tile == 0) __syncthreads();
    }
}

// ----------------------------------------------------------------------------
// hidden/out conv: mma.sync m16n8k16, M64xN=NTB*8 per warp, 3-buffer pipeline.
// TSPLIT: blockIdx.y = 16-row tile (4 stages); else blockIdx.y = nhalf (8).
// FINAL fuses z_hat/conf finalize into the epilogue.
// ----------------------------------------------------------------------------
template<int NTB, bool SILU, bool RESID, bool FINAL, bool TSPLIT>
__global__ __launch_bounds__(256, 2)
void conv_mma(const void* __restrict__ in_v, const uint32_t* __restrict__ wfrag,
              const float* __restrict__ bias, void* __restrict__ out_v,
              const void* __restrict__ resid_v,
              const float* __restrict__ latents, const int* __restrict__ idx)
{
    constexpr int CIN    = 64;
    constexpr int CHUNKS = 36;
    constexpr int BW     = CHUNKS * NTB * 64;
    constexpr int SLABS  = 4;
    constexpr int NSTAGE = TSPLIT ? SLABS : 2 * SLABS;
    constexpr bool F16OUT = (NTB == 4);

    extern __shared__ uint32_t smem[];
    uint32_t* b_s = smem;
    uint32_t* X_s = smem + BW;

    const int tid   = threadIdx.x;
    const int wid   = tid >> 5;
    const int lane  = tid & 31;
    const int n     = blockIdx.x;
    const int nhalf = TSPLIT ? 0 : blockIdx.y;
    const int tfix  = TSPLIT ? blockIdx.y : 0;
    const int tx    = lane >> 2;
    const int kq2   = (lane & 3) * 2;
    const int ch0   = F16OUT ? nhalf * 32 : 0;

    const uint32_t bs_u = smem_u32(b_s);
    const uint32_t xs_u = smem_u32(X_s);
    const char* in_b = (const char*)in_v + (size_t)n * HW * CIN * 2;

    float fs_a = 0.f, fs_s = 0.f;
    bool  fs_int = false;
    const float* L0f = nullptr;
    const float* L1f = nullptr;
    if constexpr (FINAL) {
        int t0, t1; float araw;
        seg_params(idx, n >> 7, n & 127, t0, t1, fs_a, araw);
        fs_s   = fs_a * (1.f - fs_a);
        fs_int = (araw > 0.f) && (araw < 1.f);
        L0f = latents + ((size_t)((n >> 7) * 128 + t0)) * 8 * HW;
        L1f = latents + ((size_t)((n >> 7) * 128 + t1)) * 8 * HW;
    }

    const uint32_t* wsrc = wfrag + (size_t)nhalf * CHUNKS * NTB * 64;
    for (int i = tid; i < BW / 4; i += 256)
        cp_async16(bs_u + i * 16, wsrc + i * 4, 16);

    uint32_t s_dst[5];
#pragma unroll
    for (int q = 0; q < 5; q++) {
        const int i = tid + q * 256;
        const int px = i >> 1, part = i & 1;
        s_dst[q] = (uint32_t)(px * 32 + part * 16);
    }
    int s_src[5];
    uint32_t okb = 0;
    int cached_tile = -1;

    auto stage_slab = [&](int s) {
        const int tile = TSPLIT ? tfix : (s / SLABS);
        const int k    = s & (SLABS - 1);
        if (tile != cached_tile) {
            cached_tile = tile;
            okb = 0;
#pragma unroll
            for (int q = 0; q < 5; q++) {
                const int i = tid + q * 256;
                const int px = i >> 1, part = i & 1;
                const int rr = px / 34;
                const int gx = px - rr * 34 - 1;
                const int gy = tile * 16 - 1 + rr;
                const bool ok = (gx >= 0) && (gx < 32) && (gy >= 0) && (gy < 32)
                                && (i < 1224);
                const int pix = ok ? (gy * 32 + gx) : 0;
                s_src[q] = pix * CIN * 2 + part * 16;
                okb |= (ok ? 1u : 0u) << q;
            }
        }
        const uint32_t xoff = (uint32_t)((s % 3) * 19584);
#pragma unroll
        for (int q = 0; q < 5; q++) {
            if (q < 4 || tid < 200)
                cp_async16(xs_u + xoff + s_dst[q], in_b + s_src[q] + k * 32,
                           ((okb >> q) & 1) ? 16u : 0u);
        }
        cp_commit();
    };

    stage_slab(0);
    stage_slab(1);

    float bv[NTB][2];
#pragma unroll
    for (int nt = 0; nt < NTB; nt++) {
        const int bi = ch0 + nt * 8 + kq2;
        bv[nt][0] = (F16OUT || bi     < 9) ? bias[bi]     : 0.f;
        bv[nt][1] = (F16OUT || bi + 1 < 9) ? bias[bi + 1] : 0.f;
    }

    float d[4][NTB][4];

#pragma unroll 1
    for (int s = 0; s < NSTAGE; s++) {
        const int tile = TSPLIT ? tfix : (s / SLABS);
        const int k    = s & (SLABS - 1);

        if (s + 1 < NSTAGE) cp_wait1(); else cp_wait0();
        __syncthreads();
        if (s + 2 < NSTAGE) stage_slab(s + 2);

        if (k == 0) {
#pragma unroll
            for (int f = 0; f < 4; f++)
#pragma unroll
                for (int nt = 0; nt < NTB; nt++)
#pragma unroll
                    for (int q = 0; q < 4; q++) d[f][nt][q] = 0.f;
        }

        const uint32_t* Xb = X_s + (s % 3) * 4896;
        const int cbase = (k >> 1) * 18 + (k & 1);

#pragma unroll
        for (int tap = 0; tap < 9; tap++) {
            const int dy = tap / 3, dx = tap - 3 * (tap / 3);
            const uint32_t* A = Xb + ((2 * wid + dy) * 34 + tx + dx) * 8 + kq2;
            const uint2 u0 = *(const uint2*)(A);
            const uint2 u1 = *(const uint2*)(A + 64);
            const uint2 u2 = *(const uint2*)(A + 128);
            const uint2 u3 = *(const uint2*)(A + 192);
            const uint2 u4 = *(const uint2*)(A + 272);
            const uint2 u5 = *(const uint2*)(A + 336);
            const uint2 u6 = *(const uint2*)(A + 400);
            const uint2 u7 = *(const uint2*)(A + 464);
            const uint32_t* bp = b_s + (size_t)(cbase + tap * 2) * NTB * 64 + lane * 2;
#pragma unroll
            for (int nt = 0; nt < NTB; nt++) {
                const uint2 b = *(const uint2*)(bp + nt * 64);
                mma_f16(d[0][nt], u0.x, u1.x, u0.y, u1.y, b.x, b.y);
                mma_f16(d[1][nt], u2.x, u3.x, u2.y, u3.y, b.x, b.y);
                mma_f16(d[2][nt], u4.x, u5.x, u4.y, u5.y, b.x, b.y);
                mma_f16(d[3][nt], u6.x, u7.x, u6.y, u7.y, b.x, b.y);
            }
        }

        if (k == SLABS - 1) {
#pragma unroll
            for (int f = 0; f < 4; f++) {
                const int gy = tile * 16 + 2 * wid + (f >> 1);
                const int gx = ((f & 1) << 4) + tx;
                const int p0i = gy * 32 + gx;
                const size_t gp0 = (size_t)n * HW + p0i;
                const size_t gp1 = gp0 + 8;

                if constexpr (FINAL) {
                    float* outp = (float*)out_v;
#pragma unroll
                    for (int e = 0; e < 2; e++) {
                        const int c = kq2 + e;
                        const float r0 = d[f][0][e]     + bv[0][e];
                        const float r1 = d[f][0][2 + e] + bv[0][e];
                        const float zb0 = (1.f - fs_a) * L0f[c * HW + p0i]
                                        + fs_a * L1f[c * HW + p0i];
                        const float zb1 = (1.f - fs_a) * L0f[c * HW + p0i + 8]
                                        + fs_a * L1f[c * HW + p0i + 8];
                        outp[((size_t)n * 8 + c) * HW + p0i]     = zb0 + fs_s * r0;
                        outp[((size_t)n * 8 + c) * HW + p0i + 8] = zb1 + fs_s * r1;
                    }
                    if (kq2 == 0) {
                        const float l0 = d[f][1][0] + bv[1][0];
                        const float l1 = d[f][1][2] + bv[1][0];
                        float c0 = 1.f, c1 = 1.f;
                        if (fs_int) {
                            c0 = 1.f - __fdividef(1.f, 1.f + __expf(-l0));
                            c1 = 1.f - __fdividef(1.f, 1.f + __expf(-l1));
                            c0 = fminf(fmaxf(c0, 0.f), 1.f);
                            c1 = fminf(fmaxf(c1, 0.f), 1.f);
                        }
                        float* cf = outp + (size_t)NIMG * 8 * HW + (size_t)n * HW;
                        cf[p0i]     = c0;
                        cf[p0i + 8] = c1;
                    }
                } else {
#pragma unroll
                    for (int nt = 0; nt < NTB; nt++) {
                        const int c = ch0 + nt * 8 + kq2;
                        float v00 = d[f][nt][0] + bv[nt][0];
                        float v01 = d[f][nt][1] + bv[nt][1];
                        float v10 = d[f][nt][2] + bv[nt][0];
                        float v11 = d[f][nt][3] + bv[nt][1];
                        if (SILU) {
                            v00 = __fdividef(v00, 1.f + __expf(-v00));
                            v01 = __fdividef(v01, 1.f + __expf(-v01));
                            v10 = __fdividef(v10, 1.f + __expf(-v10));
                            v11 = __fdividef(v11, 1.f + __expf(-v11));
                        }
                        const int g16 = c >> 4;
                        const int cl  = c & 15;
                        const int jl  = (((cl >> 3) & 1) << 1) | (((cl >> 1) & 3) << 2);
                        const size_t h0 = gp0 * 64 + g16 * 16 + jl;
                        const size_t h1 = gp1 * 64 + g16 * 16 + jl;
                        if (RESID) {
                            const __half2* rh = (const __half2*)resid_v;
                            const float2 r0 = __half22float2(rh[h0 >> 1]);
                            const float2 r1 = __half22float2(rh[h1 >> 1]);
                            v00 += r0.x; v01 += r0.y; v10 += r1.x; v11 += r1.y;
                        }
                        __half2* oh = (__half2*)out_v;
                        oh[h0 >> 1] = __floats2half2_rn(v00, v01);
                        oh[h1 >> 1] = __floats2half2_rn(v10, v11);
                    }
                }
            }
        }
    }
}

// ----------------------------------------------------------------------------
// launch
// ----------------------------------------------------------------------------
extern "C" void kernel_launch(void* const* d_in, const int* in_sizes, int n_in,
                              void* d_out, int out_size)
{
    const float* latents = (const float*)d_in[0];
    const int*   idx     = (const int*)d_in[1];
    const float* w_in    = (const float*)d_in[2];
    const float* b_in    = (const float*)d_in[3];
    const float* w1s     = (const float*)d_in[4];
    const float* b1s     = (const float*)d_in[5];
    const float* w2s     = (const float*)d_in[6];
    const float* b2s     = (const float*)d_in[7];
    const float* w_out   = (const float*)d_in[8];
    const float* b_out   = (const float*)d_in[9];
    float* outp = (float*)d_out;

    __half *kf, *h, *tmp;
    uint32_t *wfrag, *wfold;
    float* sfold;
    cudaGetSymbolAddress((void**)&kf,    g_kf16);
    cudaGetSymbolAddress((void**)&h,     g_h);
    cudaGetSymbolAddress((void**)&tmp,   g_tmp);
    cudaGetSymbolAddress((void**)&wfrag, g_wfrag);
    cudaGetSymbolAddress((void**)&wfold, g_wfold);
    cudaGetSymbolAddress((void**)&sfold, g_sfold);

    constexpr int SM_IN16 = ( 2304 + 3 * 4896) * 4;   // 67,968
    constexpr int SM_HID  = ( 9216 + 3 * 4896) * 4;   // 95,616
    constexpr int SM_OUT  = ( 4608 + 3 * 4896) * 4;   // 77,184

    cudaFuncSetAttribute(conv_in16,
                         cudaFuncAttributeMaxDynamicSharedMemorySize, SM_IN16);
    cudaFuncSetAttribute(conv_mma<4, true,  false, false, false>,
                         cudaFuncAttributeMaxDynamicSharedMemorySize, SM_HID);
    cudaFuncSetAttribute(conv_mma<4, false, true,  false, false>,
                         cudaFuncAttributeMaxDynamicSharedMemorySize, SM_HID);
    cudaFuncSetAttribute(conv_mma<2, false, false, true,  true>,
                         cudaFuncAttributeMaxDynamicSharedMemorySize, SM_OUT);

    kf_kernel<<<NIMG, 256>>>(latents, kf);
    fold_kernel<<<NIMG, 256>>>(w_in, idx, wfold, sfold);
    wprep_kernel<<<5, 256>>>(w1s, w2s, w_out, wfrag);

    // conv_in (fused prep): z0|z1 16ch -> 64, SiLU
    conv_in16<<<dim3(NIMG, 2), 256, SM_IN16>>>(kf, wfold, sfold, b_in, h, idx);

    for (int blk = 0; blk < 2; blk++) {
        const float* b1 = b1s + blk * 64;
        const float* b2 = b2s + blk * 64;
        conv_mma<4, true, false, false, false><<<dim3(NIMG, 2), 256, SM_HID>>>(
            h, wfrag + WOFF_HID0 + (2 * blk) * 18432, b1, tmp, nullptr, nullptr, nullptr);
        conv_mma<4, false, true, false, false><<<dim3(NIMG, 2), 256, SM_HID>>>(
            tmp, wfrag + WOFF_HID0 + (2 * blk + 1) * 18432, b2, h, h, nullptr, nullptr);
    }

    // conv_out: 64 -> 9, fused finalize, tile-split grid (512, 2)
    conv_mma<2, false, false, true, true><<<dim3(NIMG, 2), 256, SM_OUT>>>(
        h, wfrag + WOFF_OUT, b_out, outp, nullptr, latents, idx);
}

// round 15
// speedup vs baseline: 1.0437x; 1.0195x over previous
#include <cuda_runtime.h>
#include <cuda_fp16.h>
#include <cstdint>
#include <cstring>

#define NIMG 512
#define HW   1024

// ----------------------------------------------------------------------------
// scratch (device globals; no runtime allocation)
// ----------------------------------------------------------------------------
__device__ __half    g_kf16[(size_t)NIMG * HW * 8];    // latents fp16 NHWC8
__device__ __half    g_h[(size_t)NIMG * HW * 64];      // fp16 NHWC64 (permuted)
__device__ __half    g_tmp[(size_t)NIMG * HW * 64];    // fp16 NHWC64 (permuted)
__device__ uint32_t  g_wfrag[131072];                  // layers 1-5 B frags
__device__ uint32_t  g_wfold[(size_t)NIMG * 4608];     // per-image conv_in B frags
__device__ float     g_sfold[(size_t)NIMG * 576];      // per-image alpha border terms

#define WOFF_HID0 9216
#define WOFF_OUT  (9216 + 4 * 18432)   // 82944

__device__ __forceinline__ void mma_f16(float d[4], uint32_t a0, uint32_t a1,
                                        uint32_t a2, uint32_t a3,
                                        uint32_t b0, uint32_t b1) {
    asm volatile(
        "mma.sync.aligned.m16n8k16.row.col.f32.f16.f16.f32 "
        "{%0,%1,%2,%3}, {%4,%5,%6,%7}, {%8,%9}, {%0,%1,%2,%3};"
        : "+f"(d[0]), "+f"(d[1]), "+f"(d[2]), "+f"(d[3])
        : "r"(a0), "r"(a1), "r"(a2), "r"(a3), "r"(b0), "r"(b1));
}

__device__ __forceinline__ void cp_async16(uint32_t dst, const void* src, uint32_t srcsize) {
    asm volatile("cp.async.ca.shared.global [%0], [%1], 16, %2;"
                 :: "r"(dst), "l"(src), "r"(srcsize) : "memory");
}
__device__ __forceinline__ void cp_commit() {
    asm volatile("cp.async.commit_group;" ::: "memory");
}
__device__ __forceinline__ void cp_wait0() {
    asm volatile("cp.async.wait_group 0;" ::: "memory");
}
__device__ __forceinline__ void cp_wait1() {
    asm volatile("cp.async.wait_group 1;" ::: "memory");
}
__device__ __forceinline__ uint32_t smem_u32(const void* p) {
    uint32_t a;
    asm("{ .reg .u64 t; cvta.to.shared.u64 t, %1; cvt.u32.u64 %0, t; }"
        : "=r"(a) : "l"(p));
    return a;
}
__device__ __forceinline__ uint32_t h2u(__half2 h) {
    uint32_t u; memcpy(&u, &h, 4); return u;
}

// sort idx + derive segment for image (b,t)
__device__ __forceinline__ void seg_params(const int* __restrict__ idx, int b, int t,
                                           int& t0, int& t1, float& a, float& araw) {
    int v[9];
#pragma unroll
    for (int k = 0; k < 9; k++) v[k] = idx[b * 9 + k];
#pragma unroll
    for (int i = 1; i < 9; i++) {
        int key = v[i]; int j = i - 1;
        while (j >= 0 && v[j] > key) { v[j + 1] = v[j]; j--; }
        v[j + 1] = key;
    }
    int cnt = 0;
#pragma unroll
    for (int k = 0; k < 9; k++) cnt += (v[k] <= t);
    int seg = min(max(cnt - 1, 0), 7);
    t0 = v[seg]; t1 = v[seg + 1];
    araw = (float)(t - t0) / (float)max(t1 - t0, 1);
    a = fminf(fmaxf(araw, 0.f), 1.f);
}

// ----------------------------------------------------------------------------
// merged prep: blocks [0,512) kf convert, [512,1024) per-image fold,
//              [1024,1029) layer weight prep
// ----------------------------------------------------------------------------
__global__ __launch_bounds__(256)
void prep_all_kernel(const float* __restrict__ latents, const int* __restrict__ idx,
                     const float* __restrict__ w_in, const float* __restrict__ w1s,
                     const float* __restrict__ w2s, const float* __restrict__ w_out,
                     __half* __restrict__ kf, uint32_t* __restrict__ wfold,
                     float* __restrict__ sfold, uint32_t* __restrict__ wfrag)
{
    const int tid = threadIdx.x;

    if (blockIdx.x < 512) {
        // ---- kf convert ----
        const int fr = blockIdx.x;
        const float* L = latents + (size_t)fr * 8 * HW;
#pragma unroll
        for (int j = 0; j < 4; j++) {
            const int p = tid + j * 256;
            uint32_t w[4];
#pragma unroll
            for (int q = 0; q < 4; q++)
                w[q] = h2u(__floats2half2_rn(L[(2*q) * HW + p], L[(2*q+1) * HW + p]));
            *(uint4*)(kf + ((size_t)fr * HW + p) * 8) = make_uint4(w[0], w[1], w[2], w[3]);
        }
    } else if (blockIdx.x < 1024) {
        // ---- per-image conv_in fold ----
        const int n = blockIdx.x - 512;
        int t0, t1; float a, araw;
        seg_params(idx, n >> 7, n & 127, t0, t1, a, araw);

        __half* wh = (__half*)(wfold + (size_t)n * 4608);
        for (int i = tid; i < 4608; i += 256) {
            const int o   = i / 72;
            const int r   = i % 72;
            const int tap = r / 8;
            const int ci  = r % 8;
            const float W0 = w_in[(o * 25 + ci) * 9 + tap];
            const float W1 = w_in[(o * 25 + 8 + ci) * 9 + tap];
            const float W2 = w_in[(o * 25 + 16 + ci) * 9 + tap];
            const float U  = (1.f - a) * W0 + W1;
            const float V  = a * W0 + W2;
            const int kz0 = 2 * (ci >> 2) + 8 * ((ci >> 1) & 1) + (ci & 1);
#pragma unroll
            for (int h = 0; h < 2; h++) {
                const int k  = kz0 + 4 * h;
                const int hi = k >> 3, rem = k & 7, tt = rem >> 1, hf = rem & 1;
                const int lane = (o & 7) * 4 + tt;
                const int word = (o >> 5) * 2304 + (tap * 4 + ((o >> 3) & 3)) * 64 + lane * 2 + hi;
                wh[word * 2 + hf] = __float2half(h ? V : U);
            }
        }
        for (int i = tid; i < 576; i += 256) {
            const int o  = i / 9;
            const int cs = i % 9;
            const int cy = cs / 3, cx = cs % 3;
            float sum = 0.f;
#pragma unroll
            for (int dy = 0; dy < 3; dy++) {
                if ((cy == 0 && dy == 0) || (cy == 2 && dy == 2)) continue;
#pragma unroll
                for (int dx = 0; dx < 3; dx++) {
                    if ((cx == 0 && dx == 0) || (cx == 2 && dx == 2)) continue;
                    sum += w_in[(o * 25 + 24) * 9 + dy * 3 + dx];
                }
            }
            sfold[(size_t)n * 576 + cs * 64 + o] = a * sum;
        }
    } else {
        // ---- layer weight prep (layers 1..5) ----
        const int layer = blockIdx.x - 1024 + 1;
        const float* w;
        int cin, cout, woff, nwords, chunks, ntb;
        if (layer <= 4) {
            const int blk = (layer - 1) >> 1;
            w = ((layer - 1) & 1) ? (w2s + (size_t)blk * 64 * 64 * 9)
                                  : (w1s + (size_t)blk * 64 * 64 * 9);
            cin = 64; cout = 64; woff = WOFF_HID0 + (layer - 1) * 18432; nwords = 18432; chunks = 36; ntb = 4;
        } else {
            w = w_out; cin = 64; cout = 9;  woff = WOFF_OUT; nwords = 4608; chunks = 36; ntb = 2;
        }

        for (int i = tid; i < nwords; i += 256) wfrag[woff + i] = 0u;
        __syncthreads();

        __half* wh = (__half*)(wfrag);
        const int wtot = cout * cin * 9;
        for (int i = tid; i < wtot; i += 256) {
            const int tap = i % 9;
            const int ci  = (i / 9) % cin;
            const int co  = i / (9 * cin);
            const int cg  = ci >> 5;
            const int kin = ci & 31;
            const int g2  = kin >> 4;
            const int k16 = kin & 15;
            const int chunk = (cg * 9 + tap) * 2 + g2;
            const int hi  = k16 >> 3;
            const int rem = k16 & 7;
            const int tt  = rem >> 1;
            const int hf  = rem & 1;
            const int lane = (co & 7) * 4 + tt;
            int word;
            if (ntb == 4) {
                const int nhalf = co >> 5;
                const int nt4   = (co >> 3) & 3;
                word = woff + nhalf * chunks * 256 + (chunk * 4 + nt4) * 64 + lane * 2 + hi;
            } else {
                const int nt = co >> 3;
                word = woff + (chunk * 2 + nt) * 64 + lane * 2 + hi;
            }
            wh[word * 2 + hf] = __float2half(w[i]);
        }
    }
}

// ----------------------------------------------------------------------------
// conv_in (fused prep): 16 real channels (z0|z1 from kf16), per-image folded
// weights, alpha border correction (Sp cached in smem), SiLU. Grid (512, 2).
// ----------------------------------------------------------------------------
__global__ __launch_bounds__(256, 2)
void conv_in16(const __half* __restrict__ kf, const uint32_t* __restrict__ wfold,
               const float* __restrict__ sfold, const float* __restrict__ bias,
               __half* __restrict__ out, const int* __restrict__ idx)
{
    constexpr int NTB = 4;
    constexpr int BW  = 9 * NTB * 64;   // 2304 words
    extern __shared__ uint32_t smem[];
    uint32_t* b_s  = smem;
    float*    Sp_s = (float*)(smem + BW);       // 576 floats
    uint32_t* X_s  = smem + BW + 576;

    const int tid   = threadIdx.x;
    const int wid   = tid >> 5;
    const int lane  = tid & 31;
    const int n     = blockIdx.x;
    const int nhalf = blockIdx.y;
    const int tx    = lane >> 2;
    const int kq2   = (lane & 3) * 2;
    const int ch0   = nhalf * 32;

    int t0, t1; float a, araw;
    seg_params(idx, n >> 7, n & 127, t0, t1, a, araw);
    const int fb = n >> 7;
    const char* kf0 = (const char*)(kf + ((size_t)(fb * 128 + t0)) * HW * 8);
    const char* kf1 = (const char*)(kf + ((size_t)(fb * 128 + t1)) * HW * 8);
    const char* kfp = (tid & 1) ? kf1 : kf0;

    const uint32_t bs_u = smem_u32(b_s);
    const uint32_t sp_u = smem_u32(Sp_s);
    const uint32_t xs_u = smem_u32(X_s);

    const uint32_t* wsrc = wfold + (size_t)n * 4608 + nhalf * 2304;
    for (int i = tid; i < BW / 4; i += 256)
        cp_async16(bs_u + i * 16, wsrc + i * 4, 16);
    if (tid < 144)
        cp_async16(sp_u + tid * 16, sfold + (size_t)n * 576 + tid * 4, 16);

    uint32_t s_dst[5];
#pragma unroll
    for (int q = 0; q < 5; q++) {
        const int i = tid + q * 256;
        const int px = i >> 1, part = i & 1;
        s_dst[q] = (uint32_t)(px * 32 + part * 16);
    }

    auto stage_tile = [&](int tile) {
#pragma unroll
        for (int q = 0; q < 5; q++) {
            const int i = tid + q * 256;
            if (q < 4 || tid < 200) {
                const int px = i >> 1;
                const int rr = px / 34;
                const int gx = px - rr * 34 - 1;
                const int gy = tile * 16 - 1 + rr;
                const bool ok = (gx >= 0) && (gx < 32) && (gy >= 0) && (gy < 32)
                                && (i < 1224);
                const int pix = ok ? (gy * 32 + gx) : 0;
                cp_async16(xs_u + tile * 19584 + s_dst[q], kfp + (size_t)pix * 16,
                           ok ? 16u : 0u);
            }
        }
        cp_commit();
    };

    stage_tile(0);
    stage_tile(1);

    float bv[NTB][2];
#pragma unroll
    for (int nt = 0; nt < NTB; nt++) {
        bv[nt][0] = bias[ch0 + nt * 8 + kq2];
        bv[nt][1] = bias[ch0 + nt * 8 + kq2 + 1];
    }

#pragma unroll 1
    for (int tile = 0; tile < 2; tile++) {
        if (tile == 0) cp_wait1(); else cp_wait0();
        __syncthreads();

        float d[4][NTB][4];
#pragma unroll
        for (int f = 0; f < 4; f++)
#pragma unroll
            for (int nt = 0; nt < NTB; nt++)
#pragma unroll
                for (int q = 0; q < 4; q++) d[f][nt][q] = 0.f;

        const uint32_t* Xb = X_s + tile * 4896;

#pragma unroll
        for (int tap = 0; tap < 9; tap++) {
            const int dy = tap / 3, dx = tap - 3 * (tap / 3);
            const uint32_t* A = Xb + ((2 * wid + dy) * 34 + tx + dx) * 8 + kq2;
            const uint2 u0 = *(const uint2*)(A);
            const uint2 u1 = *(const uint2*)(A + 64);
            const uint2 u2 = *(const uint2*)(A + 128);
            const uint2 u3 = *(const uint2*)(A + 192);
            const uint2 u4 = *(const uint2*)(A + 272);
            const uint2 u5 = *(const uint2*)(A + 336);
            const uint2 u6 = *(const uint2*)(A + 400);
            const uint2 u7 = *(const uint2*)(A + 464);
            const uint32_t* bp = b_s + (size_t)tap * NTB * 64 + lane * 2;
#pragma unroll
            for (int nt = 0; nt < NTB; nt++) {
                const uint2 b = *(const uint2*)(bp + nt * 64);
                mma_f16(d[0][nt], u0.x, u1.x, u0.y, u1.y, b.x, b.y);
                mma_f16(d[1][nt], u2.x, u3.x, u2.y, u3.y, b.x, b.y);
                mma_f16(d[2][nt], u4.x, u5.x, u4.y, u5.y, b.x, b.y);
                mma_f16(d[3][nt], u6.x, u7.x, u6.y, u7.y, b.x, b.y);
            }
        }

#pragma unroll
        for (int f = 0; f < 4; f++) {
            const int gy  = tile * 16 + 2 * wid + (f >> 1);
            const int gx0 = ((f & 1) << 4) + tx;
            const int gx1 = gx0 + 8;
            const int cy  = (gy == 0) ? 0 : ((gy == 31) ? 2 : 1);
            const int cx0 = (gx0 == 0) ? 0 : ((gx0 == 31) ? 2 : 1);
            const int cx1 = (gx1 == 31) ? 2 : 1;
            const int base0 = (cy * 3 + cx0) * 64;
            const int base1 = (cy * 3 + cx1) * 64;
            const size_t gp0 = (size_t)n * HW + gy * 32 + gx0;
            const size_t gp1 = gp0 + 8;
#pragma unroll
            for (int nt = 0; nt < NTB; nt++) {
                const int c = ch0 + nt * 8 + kq2;
                float v00 = d[f][nt][0] + bv[nt][0] + Sp_s[base0 + c];
                float v01 = d[f][nt][1] + bv[nt][1] + Sp_s[base0 + c + 1];
                float v10 = d[f][nt][2] + bv[nt][0] + Sp_s[base1 + c];
                float v11 = d[f][nt][3] + bv[nt][1] + Sp_s[base1 + c + 1];
                v00 = __fdividef(v00, 1.f + __expf(-v00));
                v01 = __fdividef(v01, 1.f + __expf(-v01));
                v10 = __fdividef(v10, 1.f + __expf(-v10));
                v11 = __fdividef(v11, 1.f + __expf(-v11));
                const int g16 = c >> 4;
                const int cl  = c & 15;
                const int jl  = (((cl >> 3) & 1) << 1) | (((cl >> 1) & 3) << 2);
                __half2* oh = (__half2*)out;
                oh[(gp0 * 64 + g16 * 16 + jl) >> 1] = __floats2half2_rn(v00, v01);
                oh[(gp1 * 64 + g16 * 16 + jl) >> 1] = __floats2half2_rn(v10, v11);
            }
        }
        if (tile == 0) __syncthreads();
    }
}

// ----------------------------------------------------------------------------
// hidden/out conv: mma.sync m16n8k16, M64xN=NTB*8 per warp, 3-buffer pipeline.
// TSPLIT: blockIdx.y = 16-row tile (4 stages). FINAL fuses z_hat/conf.
// MINB: min blocks per SM (3 for the small conv_out).
// ----------------------------------------------------------------------------
template<int NTB, bool SILU, bool RESID, bool FINAL, bool TSPLIT, int MINB>
__global__ __launch_bounds__(256, MINB)
void conv_mma(const void* __restrict__ in_v, const uint32_t* __restrict__ wfrag,
              const float* __restrict__ bias, void* __restrict__ out_v,
              const void* __restrict__ resid_v,
              const float* __restrict__ latents, const int* __restrict__ idx)
{
    constexpr int CIN    = 64;
    constexpr int CHUNKS = 36;
    constexpr int BW     = CHUNKS * NTB * 64;
    constexpr int SLABS  = 4;
    constexpr int NSTAGE = TSPLIT ? SLABS : 2 * SLABS;
    constexpr bool F16OUT = (NTB == 4);

    extern __shared__ uint32_t smem[];
    uint32_t* b_s = smem;
    uint32_t* X_s = smem + BW;

    const int tid   = threadIdx.x;
    const int wid   = tid >> 5;
    const int lane  = tid & 31;
    const int n     = blockIdx.x;
    const int nhalf = TSPLIT ? 0 : blockIdx.y;
    const int tfix  = TSPLIT ? blockIdx.y : 0;
    const int tx    = lane >> 2;
    const int kq2   = (lane & 3) * 2;
    const int ch0   = F16OUT ? nhalf * 32 : 0;

    const uint32_t bs_u = smem_u32(b_s);
    const uint32_t xs_u = smem_u32(X_s);
    const char* in_b = (const char*)in_v + (size_t)n * HW * CIN * 2;

    float fs_a = 0.f, fs_s = 0.f;
    bool  fs_int = false;
    const float* L0f = nullptr;
    const float* L1f = nullptr;
    if constexpr (FINAL) {
        int t0, t1; float araw;
        seg_params(idx, n >> 7, n & 127, t0, t1, fs_a, araw);
        fs_s   = fs_a * (1.f - fs_a);
        fs_int = (araw > 0.f) && (araw < 1.f);
        L0f = latents + ((size_t)((n >> 7) * 128 + t0)) * 8 * HW;
        L1f = latents + ((size_t)((n >> 7) * 128 + t1)) * 8 * HW;
    }

    const uint32_t* wsrc = wfrag + (size_t)nhalf * CHUNKS * NTB * 64;
    for (int i = tid; i < BW / 4; i += 256)
        cp_async16(bs_u + i * 16, wsrc + i * 4, 16);

    uint32_t s_dst[5];
#pragma unroll
    for (int q = 0; q < 5; q++) {
        const int i = tid + q * 256;
        const int px = i >> 1, part = i & 1;
        s_dst[q] = (uint32_t)(px * 32 + part * 16);
    }
    int s_src[5];
    uint32_t okb = 0;
    int cached_tile = -1;

    auto stage_slab = [&](int s) {
        const int tile = TSPLIT ? tfix : (s / SLABS);
        const int k    = s & (SLABS - 1);
        if (tile != cached_tile) {
            cached_tile = tile;
            okb = 0;
#pragma unroll
            for (int q = 0; q < 5; q++) {
                const int i = tid + q * 256;
                const int px = i >> 1, part = i & 1;
                const int rr = px / 34;
                const int gx = px - rr * 34 - 1;
                const int gy = tile * 16 - 1 + rr;
                const bool ok = (gx >= 0) && (gx < 32) && (gy >= 0) && (gy < 32)
                                && (i < 1224);
                const int pix = ok ? (gy * 32 + gx) : 0;
                s_src[q] = pix * CIN * 2 + part * 16;
                okb |= (ok ? 1u : 0u) << q;
            }
        }
        const uint32_t xoff = (uint32_t)((s % 3) * 19584);
#pragma unroll
        for (int q = 0; q < 5; q++) {
            if (q < 4 || tid < 200)
                cp_async16(xs_u + xoff + s_dst[q], in_b + s_src[q] + k * 32,
                           ((okb >> q) & 1) ? 16u : 0u);
        }
        cp_commit();
    };

    stage_slab(0);
    stage_slab(1);

    float bv[NTB][2];
#pragma unroll
    for (int nt = 0; nt < NTB; nt++) {
        const int bi = ch0 + nt * 8 + kq2;
        bv[nt][0] = (F16OUT || bi     < 9) ? bias[bi]     : 0.f;
        bv[nt][1] = (F16OUT || bi + 1 < 9) ? bias[bi + 1] : 0.f;
    }

    float d[4][NTB][4];

#pragma unroll 1
    for (int s = 0; s < NSTAGE; s++) {
        const int tile = TSPLIT ? tfix : (s / SLABS);
        const int k    = s & (SLABS - 1);

        if (s + 1 < NSTAGE) cp_wait1(); else cp_wait0();
        __syncthreads();
        if (s + 2 < NSTAGE) stage_slab(s + 2);

        if (k == 0) {
#pragma unroll
            for (int f = 0; f < 4; f++)
#pragma unroll
                for (int nt = 0; nt < NTB; nt++)
#pragma unroll
                    for (int q = 0; q < 4; q++) d[f][nt][q] = 0.f;
        }

        const uint32_t* Xb = X_s + (s % 3) * 4896;
        const int cbase = (k >> 1) * 18 + (k & 1);

#pragma unroll
        for (int tap = 0; tap < 9; tap++) {
            const int dy = tap / 3, dx = tap - 3 * (tap / 3);
            const uint32_t* A = Xb + ((2 * wid + dy) * 34 + tx + dx) * 8 + kq2;
            const uint2 u0 = *(const uint2*)(A);
            const uint2 u1 = *(const uint2*)(A + 64);
            const uint2 u2 = *(const uint2*)(A + 128);
            const uint2 u3 = *(const uint2*)(A + 192);
            const uint2 u4 = *(const uint2*)(A + 272);
            const uint2 u5 = *(const uint2*)(A + 336);
            const uint2 u6 = *(const uint2*)(A + 400);
            const uint2 u7 = *(const uint2*)(A + 464);
            const uint32_t* bp = b_s + (size_t)(cbase + tap * 2) * NTB * 64 + lane * 2;
#pragma unroll
            for (int nt = 0; nt < NTB; nt++) {
                const uint2 b = *(const uint2*)(bp + nt * 64);
                mma_f16(d[0][nt], u0.x, u1.x, u0.y, u1.y, b.x, b.y);
                mma_f16(d[1][nt], u2.x, u3.x, u2.y, u3.y, b.x, b.y);
                mma_f16(d[2][nt], u4.x, u5.x, u4.y, u5.y, b.x, b.y);
                mma_f16(d[3][nt], u6.x, u7.x, u6.y, u7.y, b.x, b.y);
            }
        }

        if (k == SLABS - 1) {
#pragma unroll
            for (int f = 0; f < 4; f++) {
                const int gy = tile * 16 + 2 * wid + (f >> 1);
                const int gx = ((f & 1) << 4) + tx;
                const int p0i = gy * 32 + gx;
                const size_t gp0 = (size_t)n * HW + p0i;
                const size_t gp1 = gp0 + 8;

                if constexpr (FINAL) {
                    float* outp = (float*)out_v;
#pragma unroll
                    for (int e = 0; e < 2; e++) {
                        const int c = kq2 + e;
                        const float r0 = d[f][0][e]     + bv[0][e];
                        const float r1 = d[f][0][2 + e] + bv[0][e];
                        const float zb0 = (1.f - fs_a) * L0f[c * HW + p0i]
                                        + fs_a * L1f[c * HW + p0i];
                        const float zb1 = (1.f - fs_a) * L0f[c * HW + p0i + 8]
                                        + fs_a * L1f[c * HW + p0i + 8];
                        outp[((size_t)n * 8 + c) * HW + p0i]     = zb0 + fs_s * r0;
                        outp[((size_t)n * 8 + c) * HW + p0i + 8] = zb1 + fs_s * r1;
                    }
                    if (kq2 == 0) {
                        const float l0 = d[f][1][0] + bv[1][0];
                        const float l1 = d[f][1][2] + bv[1][0];
                        float c0 = 1.f, c1 = 1.f;
                        if (fs_int) {
                            c0 = 1.f - __fdividef(1.f, 1.f + __expf(-l0));
                            c1 = 1.f - __fdividef(1.f, 1.f + __expf(-l1));
                            c0 = fminf(fmaxf(c0, 0.f), 1.f);
                            c1 = fminf(fmaxf(c1, 0.f), 1.f);
                        }
                        float* cf = outp + (size_t)NIMG * 8 * HW + (size_t)n * HW;
                        cf[p0i]     = c0;
                        cf[p0i + 8] = c1;
                    }
                } else {
#pragma unroll
                    for (int nt = 0; nt < NTB; nt++) {
                        const int c = ch0 + nt * 8 + kq2;
                        float v00 = d[f][nt][0] + bv[nt][0];
                        float v01 = d[f][nt][1] + bv[nt][1];
                        float v10 = d[f][nt][2] + bv[nt][0];
                        float v11 = d[f][nt][3] + bv[nt][1];
                        if (SILU) {
                            v00 = __fdividef(v00, 1.f + __expf(-v00));
                            v01 = __fdividef(v01, 1.f + __expf(-v01));
                            v10 = __fdividef(v10, 1.f + __expf(-v10));
                            v11 = __fdividef(v11, 1.f + __expf(-v11));
                        }
                        const int g16 = c >> 4;
                        const int cl  = c & 15;
                        const int jl  = (((cl >> 3) & 1) << 1) | (((cl >> 1) & 3) << 2);
                        const size_t h0 = gp0 * 64 + g16 * 16 + jl;
                        const size_t h1 = gp1 * 64 + g16 * 16 + jl;
                        if (RESID) {
                            const __half2* rh = (const __half2*)resid_v;
                            const float2 r0 = __half22float2(rh[h0 >> 1]);
                            const float2 r1 = __half22float2(rh[h1 >> 1]);
                            v00 += r0.x; v01 += r0.y; v10 += r1.x; v11 += r1.y;
                        }
                        __half2* oh = (__half2*)out_v;
                        oh[h0 >> 1] = __floats2half2_rn(v00, v01);
                        oh[h1 >> 1] = __floats2half2_rn(v10, v11);
                    }
                }
            }
        }
    }
}

// ----------------------------------------------------------------------------
// launch
// ----------------------------------------------------------------------------
extern "C" void kernel_launch(void* const* d_in, const int* in_sizes, int n_in,
                              void* d_out, int out_size)
{
    const float* latents = (const float*)d_in[0];
    const int*   idx     = (const int*)d_in[1];
    const float* w_in    = (const float*)d_in[2];
    const float* b_in    = (const float*)d_in[3];
    const float* w1s     = (const float*)d_in[4];
    const float* b1s     = (const float*)d_in[5];
    const float* w2s     = (const float*)d_in[6];
    const float* b2s     = (const float*)d_in[7];
    const float* w_out   = (const float*)d_in[8];
    const float* b_out   = (const float*)d_in[9];
    float* outp = (float*)d_out;

    __half *kf, *h, *tmp;
    uint32_t *wfrag, *wfold;
    float* sfold;
    cudaGetSymbolAddress((void**)&kf,    g_kf16);
    cudaGetSymbolAddress((void**)&h,     g_h);
    cudaGetSymbolAddress((void**)&tmp,   g_tmp);
    cudaGetSymbolAddress((void**)&wfrag, g_wfrag);
    cudaGetSymbolAddress((void**)&wfold, g_wfold);
    cudaGetSymbolAddress((void**)&sfold, g_sfold);

    constexpr int SM_IN16 = ( 2304 + 576 + 3 * 4896) * 4;   // 70,272
    constexpr int SM_HID  = ( 9216 + 3 * 4896) * 4;         // 95,616
    constexpr int SM_OUT  = ( 4608 + 3 * 4896) * 4;         // 77,184

    cudaFuncSetAttribute(conv_in16,
                         cudaFuncAttributeMaxDynamicSharedMemorySize, SM_IN16);
    cudaFuncSetAttribute(conv_mma<4, true,  false, false, false, 2>,
                         cudaFuncAttributeMaxDynamicSharedMemorySize, SM_HID);
    cudaFuncSetAttribute(conv_mma<4, false, true,  false, false, 2>,
                         cudaFuncAttributeMaxDynamicSharedMemorySize, SM_HID);
    cudaFuncSetAttribute(conv_mma<2, false, false, true,  true,  3>,
                         cudaFuncAttributeMaxDynamicSharedMemorySize, SM_OUT);

    prep_all_kernel<<<1029, 256>>>(latents, idx, w_in, w1s, w2s, w_out,
                                   kf, wfold, sfold, wfrag);

    // conv_in (fused prep): z0|z1 16ch -> 64, SiLU
    conv_in16<<<dim3(NIMG, 2), 256, SM_IN16>>>(kf, wfold, sfold, b_in, h, idx);

    for (int blk = 0; blk < 2; blk++) {
        const float* b1 = b1s + blk * 64;
        const float* b2 = b2s + blk * 64;
        conv_mma<4, true, false, false, false, 2><<<dim3(NIMG, 2), 256, SM_HID>>>(
            h, wfrag + WOFF_HID0 + (2 * blk) * 18432, b1, tmp, nullptr, nullptr, nullptr);
        conv_mma<4, false, true, false, false, 2><<<dim3(NIMG, 2), 256, SM_HID>>>(
            tmp, wfrag + WOFF_HID0 + (2 * blk + 1) * 18432, b2, h, h, nullptr, nullptr);
    }

    // conv_out: 64 -> 9, fused finalize, tile-split grid (512, 2), 3 CTAs/SM
    conv_mma<2, false, false, true, true, 3><<<dim3(NIMG, 2), 256, SM_OUT>>>(
        h, wfrag + WOFF_OUT, b_out, outp, nullptr, latents, idx);
}

// round 16
// speedup vs baseline: 1.1276x; 1.0804x over previous
#include <cuda_runtime.h>
#include <cuda_fp16.h>
#include <cstdint>
#include <cstring>

#define NIMG 512
#define HW   1024

// ----------------------------------------------------------------------------
// scratch (device globals; no runtime allocation)
// ----------------------------------------------------------------------------
__device__ __half    g_kf16[(size_t)NIMG * HW * 8];    // latents fp16 NHWC8
__device__ __half    g_h[(size_t)NIMG * HW * 64];      // fp16 NHWC64 (permuted)
__device__ __half    g_tmp[(size_t)NIMG * HW * 64];    // fp16 NHWC64 (permuted)
__device__ uint32_t  g_wfrag[131072];                  // layers 1-5 B frags
__device__ uint32_t  g_wfold[(size_t)NIMG * 4608];     // per-image conv_in B frags
__device__ float     g_sfold[(size_t)NIMG * 576];      // per-image alpha border terms

#define WOFF_HID0 9216
#define WOFF_OUT  (9216 + 4 * 18432)   // 82944

__device__ __forceinline__ void mma_f16(float d[4], uint32_t a0, uint32_t a1,
                                        uint32_t a2, uint32_t a3,
                                        uint32_t b0, uint32_t b1) {
    asm volatile(
        "mma.sync.aligned.m16n8k16.row.col.f32.f16.f16.f32 "
        "{%0,%1,%2,%3}, {%4,%5,%6,%7}, {%8,%9}, {%0,%1,%2,%3};"
        : "+f"(d[0]), "+f"(d[1]), "+f"(d[2]), "+f"(d[3])
        : "r"(a0), "r"(a1), "r"(a2), "r"(a3), "r"(b0), "r"(b1));
}

__device__ __forceinline__ void cp_async16(uint32_t dst, const void* src, uint32_t srcsize) {
    asm volatile("cp.async.ca.shared.global [%0], [%1], 16, %2;"
                 :: "r"(dst), "l"(src), "r"(srcsize) : "memory");
}
__device__ __forceinline__ void cp_commit() {
    asm volatile("cp.async.commit_group;" ::: "memory");
}
__device__ __forceinline__ void cp_wait0() {
    asm volatile("cp.async.wait_group 0;" ::: "memory");
}
__device__ __forceinline__ void cp_wait1() {
    asm volatile("cp.async.wait_group 1;" ::: "memory");
}
__device__ __forceinline__ uint32_t smem_u32(const void* p) {
    uint32_t a;
    asm("{ .reg .u64 t; cvta.to.shared.u64 t, %1; cvt.u32.u64 %0, t; }"
        : "=r"(a) : "l"(p));
    return a;
}
__device__ __forceinline__ uint32_t h2u(__half2 h) {
    uint32_t u; memcpy(&u, &h, 4); return u;
}
__device__ __forceinline__ float2 u2f2(uint32_t u) {
    __half2 h; memcpy(&h, &u, 4); return __half22float2(h);
}

// sort idx + derive segment for image (b,t)
__device__ __forceinline__ void seg_params(const int* __restrict__ idx, int b, int t,
                                           int& t0, int& t1, float& a, float& araw) {
    int v[9];
#pragma unroll
    for (int k = 0; k < 9; k++) v[k] = idx[b * 9 + k];
#pragma unroll
    for (int i = 1; i < 9; i++) {
        int key = v[i]; int j = i - 1;
        while (j >= 0 && v[j] > key) { v[j + 1] = v[j]; j--; }
        v[j + 1] = key;
    }
    int cnt = 0;
#pragma unroll
    for (int k = 0; k < 9; k++) cnt += (v[k] <= t);
    int seg = min(max(cnt - 1, 0), 7);
    t0 = v[seg]; t1 = v[seg + 1];
    araw = (float)(t - t0) / (float)max(t1 - t0, 1);
    a = fminf(fmaxf(araw, 0.f), 1.f);
}

// ----------------------------------------------------------------------------
// merged prep: blocks [0,512) kf convert, [512,1024) per-image fold,
//              [1024,1029) layer weight prep
// ----------------------------------------------------------------------------
__global__ __launch_bounds__(256)
void prep_all_kernel(const float* __restrict__ latents, const int* __restrict__ idx,
                     const float* __restrict__ w_in, const float* __restrict__ w1s,
                     const float* __restrict__ w2s, const float* __restrict__ w_out,
                     __half* __restrict__ kf, uint32_t* __restrict__ wfold,
                     float* __restrict__ sfold, uint32_t* __restrict__ wfrag)
{
    const int tid = threadIdx.x;

    if (blockIdx.x < 512) {
        const int fr = blockIdx.x;
        const float* L = latents + (size_t)fr * 8 * HW;
#pragma unroll
        for (int j = 0; j < 4; j++) {
            const int p = tid + j * 256;
            uint32_t w[4];
#pragma unroll
            for (int q = 0; q < 4; q++)
                w[q] = h2u(__floats2half2_rn(L[(2*q) * HW + p], L[(2*q+1) * HW + p]));
            *(uint4*)(kf + ((size_t)fr * HW + p) * 8) = make_uint4(w[0], w[1], w[2], w[3]);
        }
    } else if (blockIdx.x < 1024) {
        const int n = blockIdx.x - 512;
        int t0, t1; float a, araw;
        seg_params(idx, n >> 7, n & 127, t0, t1, a, araw);

        __half* wh = (__half*)(wfold + (size_t)n * 4608);
        for (int i = tid; i < 4608; i += 256) {
            const int o   = i / 72;
            const int r   = i % 72;
            const int tap = r / 8;
            const int ci  = r % 8;
            const float W0 = w_in[(o * 25 + ci) * 9 + tap];
            const float W1 = w_in[(o * 25 + 8 + ci) * 9 + tap];
            const float W2 = w_in[(o * 25 + 16 + ci) * 9 + tap];
            const float U  = (1.f - a) * W0 + W1;
            const float V  = a * W0 + W2;
            const int kz0 = 2 * (ci >> 2) + 8 * ((ci >> 1) & 1) + (ci & 1);
#pragma unroll
            for (int h = 0; h < 2; h++) {
                const int k  = kz0 + 4 * h;
                const int hi = k >> 3, rem = k & 7, tt = rem >> 1, hf = rem & 1;
                const int lane = (o & 7) * 4 + tt;
                const int word = (o >> 5) * 2304 + (tap * 4 + ((o >> 3) & 3)) * 64 + lane * 2 + hi;
                wh[word * 2 + hf] = __float2half(h ? V : U);
            }
        }
        for (int i = tid; i < 576; i += 256) {
            const int o  = i / 9;
            const int cs = i % 9;
            const int cy = cs / 3, cx = cs % 3;
            float sum = 0.f;
#pragma unroll
            for (int dy = 0; dy < 3; dy++) {
                if ((cy == 0 && dy == 0) || (cy == 2 && dy == 2)) continue;
#pragma unroll
                for (int dx = 0; dx < 3; dx++) {
                    if ((cx == 0 && dx == 0) || (cx == 2 && dx == 2)) continue;
                    sum += w_in[(o * 25 + 24) * 9 + dy * 3 + dx];
                }
            }
            sfold[(size_t)n * 576 + cs * 64 + o] = a * sum;
        }
    } else {
        const int layer = blockIdx.x - 1024 + 1;
        const float* w;
        int cin, cout, woff, nwords, chunks, ntb;
        if (layer <= 4) {
            const int blk = (layer - 1) >> 1;
            w = ((layer - 1) & 1) ? (w2s + (size_t)blk * 64 * 64 * 9)
                                  : (w1s + (size_t)blk * 64 * 64 * 9);
            cin = 64; cout = 64; woff = WOFF_HID0 + (layer - 1) * 18432; nwords = 18432; chunks = 36; ntb = 4;
        } else {
            w = w_out; cin = 64; cout = 9;  woff = WOFF_OUT; nwords = 4608; chunks = 36; ntb = 2;
        }

        for (int i = tid; i < nwords; i += 256) wfrag[woff + i] = 0u;
        __syncthreads();

        __half* wh = (__half*)(wfrag);
        const int wtot = cout * cin * 9;
        for (int i = tid; i < wtot; i += 256) {
            const int tap = i % 9;
            const int ci  = (i / 9) % cin;
            const int co  = i / (9 * cin);
            const int cg  = ci >> 5;
            const int kin = ci & 31;
            const int g2  = kin >> 4;
            const int k16 = kin & 15;
            const int chunk = (cg * 9 + tap) * 2 + g2;
            const int hi  = k16 >> 3;
            const int rem = k16 & 7;
            const int tt  = rem >> 1;
            const int hf  = rem & 1;
            const int lane = (co & 7) * 4 + tt;
            int word;
            if (ntb == 4) {
                const int nhalf = co >> 5;
                const int nt4   = (co >> 3) & 3;
                word = woff + nhalf * chunks * 256 + (chunk * 4 + nt4) * 64 + lane * 2 + hi;
            } else {
                const int nt = co >> 3;
                word = woff + (chunk * 2 + nt) * 64 + lane * 2 + hi;
            }
            wh[word * 2 + hf] = __float2half(w[i]);
        }
    }
}

// ----------------------------------------------------------------------------
// conv_in (fused prep): 16 real channels (z0|z1 from kf16), per-image folded
// weights, alpha border correction (Sp in smem), SiLU. Grid (512, 2).
// Epilogue uses uint2 (8B) stores.
// ----------------------------------------------------------------------------
__global__ __launch_bounds__(256, 2)
void conv_in16(const __half* __restrict__ kf, const uint32_t* __restrict__ wfold,
               const float* __restrict__ sfold, const float* __restrict__ bias,
               __half* __restrict__ out, const int* __restrict__ idx)
{
    constexpr int NTB = 4;
    constexpr int BW  = 9 * NTB * 64;   // 2304 words
    extern __shared__ uint32_t smem[];
    uint32_t* b_s  = smem;
    float*    Sp_s = (float*)(smem + BW);       // 576 floats
    uint32_t* X_s  = smem + BW + 576;

    const int tid   = threadIdx.x;
    const int wid   = tid >> 5;
    const int lane  = tid & 31;
    const int n     = blockIdx.x;
    const int nhalf = blockIdx.y;
    const int tx    = lane >> 2;
    const int kq2   = (lane & 3) * 2;
    const int ch0   = nhalf * 32;

    int t0, t1; float a, araw;
    seg_params(idx, n >> 7, n & 127, t0, t1, a, araw);
    const int fb = n >> 7;
    const char* kf0 = (const char*)(kf + ((size_t)(fb * 128 + t0)) * HW * 8);
    const char* kf1 = (const char*)(kf + ((size_t)(fb * 128 + t1)) * HW * 8);
    const char* kfp = (tid & 1) ? kf1 : kf0;

    const uint32_t bs_u = smem_u32(b_s);
    const uint32_t sp_u = smem_u32(Sp_s);
    const uint32_t xs_u = smem_u32(X_s);

    const uint32_t* wsrc = wfold + (size_t)n * 4608 + nhalf * 2304;
    for (int i = tid; i < BW / 4; i += 256)
        cp_async16(bs_u + i * 16, wsrc + i * 4, 16);
    if (tid < 144)
        cp_async16(sp_u + tid * 16, sfold + (size_t)n * 576 + tid * 4, 16);

    uint32_t s_dst[5];
#pragma unroll
    for (int q = 0; q < 5; q++) {
        const int i = tid + q * 256;
        const int px = i >> 1, part = i & 1;
        s_dst[q] = (uint32_t)(px * 32 + part * 16);
    }

    auto stage_tile = [&](int tile) {
#pragma unroll
        for (int q = 0; q < 5; q++) {
            const int i = tid + q * 256;
            if (q < 4 || tid < 200) {
                const int px = i >> 1;
                const int rr = px / 34;
                const int gx = px - rr * 34 - 1;
                const int gy = tile * 16 - 1 + rr;
                const bool ok = (gx >= 0) && (gx < 32) && (gy >= 0) && (gy < 32)
                                && (i < 1224);
                const int pix = ok ? (gy * 32 + gx) : 0;
                cp_async16(xs_u + tile * 19584 + s_dst[q], kfp + (size_t)pix * 16,
                           ok ? 16u : 0u);
            }
        }
        cp_commit();
    };

    stage_tile(0);
    stage_tile(1);

    float bv[NTB][2];
#pragma unroll
    for (int nt = 0; nt < NTB; nt++) {
        bv[nt][0] = bias[ch0 + nt * 8 + kq2];
        bv[nt][1] = bias[ch0 + nt * 8 + kq2 + 1];
    }

#pragma unroll 1
    for (int tile = 0; tile < 2; tile++) {
        if (tile == 0) cp_wait1(); else cp_wait0();
        __syncthreads();

        float d[4][NTB][4];
#pragma unroll
        for (int f = 0; f < 4; f++)
#pragma unroll
            for (int nt = 0; nt < NTB; nt++)
#pragma unroll
                for (int q = 0; q < 4; q++) d[f][nt][q] = 0.f;

        const uint32_t* Xb = X_s + tile * 4896;

#pragma unroll
        for (int tap = 0; tap < 9; tap++) {
            const int dy = tap / 3, dx = tap - 3 * (tap / 3);
            const uint32_t* A = Xb + ((2 * wid + dy) * 34 + tx + dx) * 8 + kq2;
            const uint2 u0 = *(const uint2*)(A);
            const uint2 u1 = *(const uint2*)(A + 64);
            const uint2 u2 = *(const uint2*)(A + 128);
            const uint2 u3 = *(const uint2*)(A + 192);
            const uint2 u4 = *(const uint2*)(A + 272);
            const uint2 u5 = *(const uint2*)(A + 336);
            const uint2 u6 = *(const uint2*)(A + 400);
            const uint2 u7 = *(const uint2*)(A + 464);
            const uint32_t* bp = b_s + (size_t)tap * NTB * 64 + lane * 2;
#pragma unroll
            for (int nt = 0; nt < NTB; nt++) {
                const uint2 b = *(const uint2*)(bp + nt * 64);
                mma_f16(d[0][nt], u0.x, u1.x, u0.y, u1.y, b.x, b.y);
                mma_f16(d[1][nt], u2.x, u3.x, u2.y, u3.y, b.x, b.y);
                mma_f16(d[2][nt], u4.x, u5.x, u4.y, u5.y, b.x, b.y);
                mma_f16(d[3][nt], u6.x, u7.x, u6.y, u7.y, b.x, b.y);
            }
        }

#pragma unroll
        for (int f = 0; f < 4; f++) {
            const int gy  = tile * 16 + 2 * wid + (f >> 1);
            const int gx0 = ((f & 1) << 4) + tx;
            const int gx1 = gx0 + 8;
            const int cy  = (gy == 0) ? 0 : ((gy == 31) ? 2 : 1);
            const int cx0 = (gx0 == 0) ? 0 : ((gx0 == 31) ? 2 : 1);
            const int cx1 = (gx1 == 31) ? 2 : 1;
            const int base0 = (cy * 3 + cx0) * 64;
            const int base1 = (cy * 3 + cx1) * 64;
            const size_t gp0 = (size_t)n * HW + gy * 32 + gx0;
            const size_t gp1 = gp0 + 8;
#pragma unroll
            for (int gp16 = 0; gp16 < 2; gp16++) {
                const int nt0 = 2 * gp16, nt1 = nt0 + 1;
                const int c0 = ch0 + nt0 * 8 + kq2;
                const int c1 = c0 + 8;
                const int g16 = (ch0 >> 4) + gp16;
                float v00 = d[f][nt0][0] + bv[nt0][0] + Sp_s[base0 + c0];
                float v01 = d[f][nt0][1] + bv[nt0][1] + Sp_s[base0 + c0 + 1];
                float v02 = d[f][nt1][0] + bv[nt1][0] + Sp_s[base0 + c1];
                float v03 = d[f][nt1][1] + bv[nt1][1] + Sp_s[base0 + c1 + 1];
                float v10 = d[f][nt0][2] + bv[nt0][0] + Sp_s[base1 + c0];
                float v11 = d[f][nt0][3] + bv[nt0][1] + Sp_s[base1 + c0 + 1];
                float v12 = d[f][nt1][2] + bv[nt1][0] + Sp_s[base1 + c1];
                float v13 = d[f][nt1][3] + bv[nt1][1] + Sp_s[base1 + c1 + 1];
                v00 = __fdividef(v00, 1.f + __expf(-v00));
                v01 = __fdividef(v01, 1.f + __expf(-v01));
                v02 = __fdividef(v02, 1.f + __expf(-v02));
                v03 = __fdividef(v03, 1.f + __expf(-v03));
                v10 = __fdividef(v10, 1.f + __expf(-v10));
                v11 = __fdividef(v11, 1.f + __expf(-v11));
                v12 = __fdividef(v12, 1.f + __expf(-v12));
                v13 = __fdividef(v13, 1.f + __expf(-v13));
                const size_t w0 = gp0 * 64 + g16 * 16 + kq2 * 2;   // half units
                const size_t w1 = gp1 * 64 + g16 * 16 + kq2 * 2;
                uint2 s0, s1;
                s0.x = h2u(__floats2half2_rn(v00, v01));
                s0.y = h2u(__floats2half2_rn(v02, v03));
                s1.x = h2u(__floats2half2_rn(v10, v11));
                s1.y = h2u(__floats2half2_rn(v12, v13));
                *(uint2*)(out + w0) = s0;
                *(uint2*)(out + w1) = s1;
            }
        }
        if (tile == 0) __syncthreads();
    }
}

// ----------------------------------------------------------------------------
// hidden/out conv: mma.sync m16n8k16, M64xN=NTB*8 per warp, 3-buffer pipeline.
// TSPLIT: blockIdx.y = 16-row tile (4 stages). FINAL fuses z_hat/conf.
// MINB: min blocks per SM. F16OUT epilogue uses uint2 (8B) loads/stores.
// ----------------------------------------------------------------------------
template<int NTB, bool SILU, bool RESID, bool FINAL, bool TSPLIT, int MINB>
__global__ __launch_bounds__(256, MINB)
void conv_mma(const void* __restrict__ in_v, const uint32_t* __restrict__ wfrag,
              const float* __restrict__ bias, void* __restrict__ out_v,
              const void* __restrict__ resid_v,
              const float* __restrict__ latents, const int* __restrict__ idx)
{
    constexpr int CIN    = 64;
    constexpr int CHUNKS = 36;
    constexpr int BW     = CHUNKS * NTB * 64;
    constexpr int SLABS  = 4;
    constexpr int NSTAGE = TSPLIT ? SLABS : 2 * SLABS;
    constexpr bool F16OUT = (NTB == 4);

    extern __shared__ uint32_t smem[];
    uint32_t* b_s = smem;
    uint32_t* X_s = smem + BW;

    const int tid   = threadIdx.x;
    const int wid   = tid >> 5;
    const int lane  = tid & 31;
    const int n     = blockIdx.x;
    const int nhalf = TSPLIT ? 0 : blockIdx.y;
    const int tfix  = TSPLIT ? blockIdx.y : 0;
    const int tx    = lane >> 2;
    const int kq2   = (lane & 3) * 2;
    const int ch0   = F16OUT ? nhalf * 32 : 0;

    const uint32_t bs_u = smem_u32(b_s);
    const uint32_t xs_u = smem_u32(X_s);
    const char* in_b = (const char*)in_v + (size_t)n * HW * CIN * 2;

    float fs_a = 0.f, fs_s = 0.f;
    bool  fs_int = false;
    const float* L0f = nullptr;
    const float* L1f = nullptr;
    if constexpr (FINAL) {
        int t0, t1; float araw;
        seg_params(idx, n >> 7, n & 127, t0, t1, fs_a, araw);
        fs_s   = fs_a * (1.f - fs_a);
        fs_int = (araw > 0.f) && (araw < 1.f);
        L0f = latents + ((size_t)((n >> 7) * 128 + t0)) * 8 * HW;
        L1f = latents + ((size_t)((n >> 7) * 128 + t1)) * 8 * HW;
    }

    const uint32_t* wsrc = wfrag + (size_t)nhalf * CHUNKS * NTB * 64;
    for (int i = tid; i < BW / 4; i += 256)
        cp_async16(bs_u + i * 16, wsrc + i * 4, 16);

    uint32_t s_dst[5];
#pragma unroll
    for (int q = 0; q < 5; q++) {
        const int i = tid + q * 256;
        const int px = i >> 1, part = i & 1;
        s_dst[q] = (uint32_t)(px * 32 + part * 16);
    }
    int s_src[5];
    uint32_t okb = 0;
    int cached_tile = -1;

    auto stage_slab = [&](int s) {
        const int tile = TSPLIT ? tfix : (s / SLABS);
        const int k    = s & (SLABS - 1);
        if (tile != cached_tile) {
            cached_tile = tile;
            okb = 0;
#pragma unroll
            for (int q = 0; q < 5; q++) {
                const int i = tid + q * 256;
                const int px = i >> 1, part = i & 1;
                const int rr = px / 34;
                const int gx = px - rr * 34 - 1;
                const int gy = tile * 16 - 1 + rr;
                const bool ok = (gx >= 0) && (gx < 32) && (gy >= 0) && (gy < 32)
                                && (i < 1224);
                const int pix = ok ? (gy * 32 + gx) : 0;
                s_src[q] = pix * CIN * 2 + part * 16;
                okb |= (ok ? 1u : 0u) << q;
            }
        }
        const uint32_t xoff = (uint32_t)((s % 3) * 19584);
#pragma unroll
        for (int q = 0; q < 5; q++) {
            if (q < 4 || tid < 200)
                cp_async16(xs_u + xoff + s_dst[q], in_b + s_src[q] + k * 32,
                           ((okb >> q) & 1) ? 16u : 0u);
        }
        cp_commit();
    };

    stage_slab(0);
    stage_slab(1);

    float bv[NTB][2];
#pragma unroll
    for (int nt = 0; nt < NTB; nt++) {
        const int bi = ch0 + nt * 8 + kq2;
        bv[nt][0] = (F16OUT || bi     < 9) ? bias[bi]     : 0.f;
        bv[nt][1] = (F16OUT || bi + 1 < 9) ? bias[bi + 1] : 0.f;
    }

    float d[4][NTB][4];

#pragma unroll 1
    for (int s = 0; s < NSTAGE; s++) {
        const int tile = TSPLIT ? tfix : (s / SLABS);
        const int k    = s & (SLABS - 1);

        if (s + 1 < NSTAGE) cp_wait1(); else cp_wait0();
        __syncthreads();
        if (s + 2 < NSTAGE) stage_slab(s + 2);

        if (k == 0) {
#pragma unroll
            for (int f = 0; f < 4; f++)
#pragma unroll
                for (int nt = 0; nt < NTB; nt++)
#pragma unroll
                    for (int q = 0; q < 4; q++) d[f][nt][q] = 0.f;
        }

        const uint32_t* Xb = X_s + (s % 3) * 4896;
        const int cbase = (k >> 1) * 18 + (k & 1);

#pragma unroll
        for (int tap = 0; tap < 9; tap++) {
            const int dy = tap / 3, dx = tap - 3 * (tap / 3);
            const uint32_t* A = Xb + ((2 * wid + dy) * 34 + tx + dx) * 8 + kq2;
            const uint2 u0 = *(const uint2*)(A);
            const uint2 u1 = *(const uint2*)(A + 64);
            const uint2 u2 = *(const uint2*)(A + 128);
            const uint2 u3 = *(const uint2*)(A + 192);
            const uint2 u4 = *(const uint2*)(A + 272);
            const uint2 u5 = *(const uint2*)(A + 336);
            const uint2 u6 = *(const uint2*)(A + 400);
            const uint2 u7 = *(const uint2*)(A + 464);
            const uint32_t* bp = b_s + (size_t)(cbase + tap * 2) * NTB * 64 + lane * 2;
#pragma unroll
            for (int nt = 0; nt < NTB; nt++) {
                const uint2 b = *(const uint2*)(bp + nt * 64);
                mma_f16(d[0][nt], u0.x, u1.x, u0.y, u1.y, b.x, b.y);
                mma_f16(d[1][nt], u2.x, u3.x, u2.y, u3.y, b.x, b.y);
                mma_f16(d[2][nt], u4.x, u5.x, u4.y, u5.y, b.x, b.y);
                mma_f16(d[3][nt], u6.x, u7.x, u6.y, u7.y, b.x, b.y);
            }
        }

        if (k == SLABS - 1) {
#pragma unroll
            for (int f = 0; f < 4; f++) {
                const int gy = tile * 16 + 2 * wid + (f >> 1);
                const int gx = ((f & 1) << 4) + tx;
                const int p0i = gy * 32 + gx;
                const size_t gp0 = (size_t)n * HW + p0i;
                const size_t gp1 = gp0 + 8;

                if constexpr (FINAL) {
                    float* outp = (float*)out_v;
#pragma unroll
                    for (int e = 0; e < 2; e++) {
                        const int c = kq2 + e;
                        const float r0 = d[f][0][e]     + bv[0][e];
                        const float r1 = d[f][0][2 + e] + bv[0][e];
                        const float zb0 = (1.f - fs_a) * L0f[c * HW + p0i]
                                        + fs_a * L1f[c * HW + p0i];
                        const float zb1 = (1.f - fs_a) * L0f[c * HW + p0i + 8]
                                        + fs_a * L1f[c * HW + p0i + 8];
                        outp[((size_t)n * 8 + c) * HW + p0i]     = zb0 + fs_s * r0;
                        outp[((size_t)n * 8 + c) * HW + p0i + 8] = zb1 + fs_s * r1;
                    }
                    if (kq2 == 0) {
                        const float l0 = d[f][1][0] + bv[1][0];
                        const float l1 = d[f][1][2] + bv[1][0];
                        float c0 = 1.f, c1 = 1.f;
                        if (fs_int) {
                            c0 = 1.f - __fdividef(1.f, 1.f + __expf(-l0));
                            c1 = 1.f - __fdividef(1.f, 1.f + __expf(-l1));
                            c0 = fminf(fmaxf(c0, 0.f), 1.f);
                            c1 = fminf(fmaxf(c1, 0.f), 1.f);
                        }
                        float* cf = outp + (size_t)NIMG * 8 * HW + (size_t)n * HW;
                        cf[p0i]     = c0;
                        cf[p0i + 8] = c1;
                    }
                } else {
                    __half* oh = (__half*)out_v;
#pragma unroll
                    for (int gp16 = 0; gp16 < NTB / 2; gp16++) {
                        const int nt0 = 2 * gp16, nt1 = nt0 + 1;
                        const int g16 = (ch0 >> 4) + gp16;
                        float v00 = d[f][nt0][0] + bv[nt0][0];
                        float v01 = d[f][nt0][1] + bv[nt0][1];
                        float v02 = d[f][nt1][0] + bv[nt1][0];
                        float v03 = d[f][nt1][1] + bv[nt1][1];
                        float v10 = d[f][nt0][2] + bv[nt0][0];
                        float v11 = d[f][nt0][3] + bv[nt0][1];
                        float v12 = d[f][nt1][2] + bv[nt1][0];
                        float v13 = d[f][nt1][3] + bv[nt1][1];
                        if (SILU) {
                            v00 = __fdividef(v00, 1.f + __expf(-v00));
                            v01 = __fdividef(v01, 1.f + __expf(-v01));
                            v02 = __fdividef(v02, 1.f + __expf(-v02));
                            v03 = __fdividef(v03, 1.f + __expf(-v03));
                            v10 = __fdividef(v10, 1.f + __expf(-v10));
                            v11 = __fdividef(v11, 1.f + __expf(-v11));
                            v12 = __fdividef(v12, 1.f + __expf(-v12));
                            v13 = __fdividef(v13, 1.f + __expf(-v13));
                        }
                        const size_t w0 = gp0 * 64 + g16 * 16 + kq2 * 2;  // half units
                        const size_t w1 = gp1 * 64 + g16 * 16 + kq2 * 2;
                        if (RESID) {
                            const uint2 r0 = *(const uint2*)((const __half*)resid_v + w0);
                            const uint2 r1 = *(const uint2*)((const __half*)resid_v + w1);
                            const float2 a0 = u2f2(r0.x), a1 = u2f2(r0.y);
                            const float2 a2 = u2f2(r1.x), a3 = u2f2(r1.y);
                            v00 += a0.x; v01 += a0.y; v02 += a1.x; v03 += a1.y;
                            v10 += a2.x; v11 += a2.y; v12 += a3.x; v13 += a3.y;
                        }
                        uint2 s0, s1;
                        s0.x = h2u(__floats2half2_rn(v00, v01));
                        s0.y = h2u(__floats2half2_rn(v02, v03));
                        s1.x = h2u(__floats2half2_rn(v10, v11));
                        s1.y = h2u(__floats2half2_rn(v12, v13));
                        *(uint2*)(oh + w0) = s0;
                        *(uint2*)(oh + w1) = s1;
                    }
                }
            }
        }
    }
}

// ----------------------------------------------------------------------------
// launch
// ----------------------------------------------------------------------------
extern "C" void kernel_launch(void* const* d_in, const int* in_sizes, int n_in,
                              void* d_out, int out_size)
{
    const float* latents = (const float*)d_in[0];
    const int*   idx     = (const int*)d_in[1];
    const float* w_in    = (const float*)d_in[2];
    const float* b_in    = (const float*)d_in[3];
    const float* w1s     = (const float*)d_in[4];
    const float* b1s     = (const float*)d_in[5];
    const float* w2s     = (const float*)d_in[6];
    const float* b2s     = (const float*)d_in[7];
    const float* w_out   = (const float*)d_in[8];
    const float* b_out   = (const float*)d_in[9];
    float* outp = (float*)d_out;

    __half *kf, *h, *tmp;
    uint32_t *wfrag, *wfold;
    float* sfold;
    cudaGetSymbolAddress((void**)&kf,    g_kf16);
    cudaGetSymbolAddress((void**)&h,     g_h);
    cudaGetSymbolAddress((void**)&tmp,   g_tmp);
    cudaGetSymbolAddress((void**)&wfrag, g_wfrag);
    cudaGetSymbolAddress((void**)&wfold, g_wfold);
    cudaGetSymbolAddress((void**)&sfold, g_sfold);

    constexpr int SM_IN16 = ( 2304 + 576 + 3 * 4896) * 4;   // 70,272
    constexpr int SM_HID  = ( 9216 + 3 * 4896) * 4;         // 95,616
    constexpr int SM_OUT  = ( 4608 + 3 * 4896) * 4;         // 77,184

    cudaFuncSetAttribute(conv_in16,
                         cudaFuncAttributeMaxDynamicSharedMemorySize, SM_IN16);
    cudaFuncSetAttribute(conv_mma<4, true,  false, false, false, 2>,
                         cudaFuncAttributeMaxDynamicSharedMemorySize, SM_HID);
    cudaFuncSetAttribute(conv_mma<4, false, true,  false, false, 2>,
                         cudaFuncAttributeMaxDynamicSharedMemorySize, SM_HID);
    cudaFuncSetAttribute(conv_mma<2, false, false, true,  true,  3>,
                         cudaFuncAttributeMaxDynamicSharedMemorySize, SM_OUT);

    prep_all_kernel<<<1029, 256>>>(latents, idx, w_in, w1s, w2s, w_out,
                                   kf, wfold, sfold, wfrag);

    // conv_in (fused prep): z0|z1 16ch -> 64, SiLU
    conv_in16<<<dim3(NIMG, 2), 256, SM_IN16>>>(kf, wfold, sfold, b_in, h, idx);

    for (int blk = 0; blk < 2; blk++) {
        const float* b1 = b1s + blk * 64;
        const float* b2 = b2s + blk * 64;
        conv_mma<4, true, false, false, false, 2><<<dim3(NIMG, 2), 256, SM_HID>>>(
            h, wfrag + WOFF_HID0 + (2 * blk) * 18432, b1, tmp, nullptr, nullptr, nullptr);
        conv_mma<4, false, true, false, false, 2><<<dim3(NIMG, 2), 256, SM_HID>>>(
            tmp, wfrag + WOFF_HID0 + (2 * blk + 1) * 18432, b2, h, h, nullptr, nullptr);
    }

    // conv_out: 64 -> 9, fused finalize, tile-split grid (512, 2), 3 CTAs/SM
    conv_mma<2, false, false, true, true, 3><<<dim3(NIMG, 2), 256, SM_OUT>>>(
        h, wfrag + WOFF_OUT, b_out, outp, nullptr, latents, idx);
}

// round 17
// speedup vs baseline: 1.2671x; 1.1237x over previous
#include <cuda_runtime.h>
#include <cuda_fp16.h>
#include <cstdint>
#include <cstring>

#define NIMG 512
#define HW   1024

// ----------------------------------------------------------------------------
// scratch (device globals; no runtime allocation)
// ----------------------------------------------------------------------------
__device__ __half    g_kf16[(size_t)NIMG * HW * 8];    // latents fp16 NHWC8
__device__ __half    g_h[(size_t)NIMG * HW * 64];      // fp16 NHWC64 (permuted)
__device__ __half    g_tmp[(size_t)NIMG * HW * 64];    // fp16 NHWC64 (permuted)
__device__ uint32_t  g_wfrag[131072];                  // layers 1-5 B frags
__device__ uint32_t  g_wfold[(size_t)NIMG * 4608];     // per-image conv_in B frags
__device__ float     g_sfold[(size_t)NIMG * 576];      // per-image alpha border terms

#define WOFF_HID0 9216
#define WOFF_OUT  (9216 + 4 * 18432)   // 82944

__device__ __forceinline__ void mma_f16(float d[4], uint32_t a0, uint32_t a1,
                                        uint32_t a2, uint32_t a3,
                                        uint32_t b0, uint32_t b1) {
    asm volatile(
        "mma.sync.aligned.m16n8k16.row.col.f32.f16.f16.f32 "
        "{%0,%1,%2,%3}, {%4,%5,%6,%7}, {%8,%9}, {%0,%1,%2,%3};"
        : "+f"(d[0]), "+f"(d[1]), "+f"(d[2]), "+f"(d[3])
        : "r"(a0), "r"(a1), "r"(a2), "r"(a3), "r"(b0), "r"(b1));
}

__device__ __forceinline__ void cp_async16(uint32_t dst, const void* src, uint32_t srcsize) {
    asm volatile("cp.async.cg.shared.global [%0], [%1], 16, %2;"
                 :: "r"(dst), "l"(src), "r"(srcsize) : "memory");
}
__device__ __forceinline__ void cp_commit() {
    asm volatile("cp.async.commit_group;" ::: "memory");
}
__device__ __forceinline__ void cp_wait0() {
    asm volatile("cp.async.wait_group 0;" ::: "memory");
}
__device__ __forceinline__ void cp_wait1() {
    asm volatile("cp.async.wait_group 1;" ::: "memory");
}
__device__ __forceinline__ uint32_t smem_u32(const void* p) {
    uint32_t a;
    asm("{ .reg .u64 t; cvta.to.shared.u64 t, %1; cvt.u32.u64 %0, t; }"
        : "=r"(a) : "l"(p));
    return a;
}
__device__ __forceinline__ uint32_t h2u(__half2 h) {
    uint32_t u; memcpy(&u, &h, 4); return u;
}
__device__ __forceinline__ float2 u2f2(uint32_t u) {
    __half2 h; memcpy(&h, &u, 4); return __half22float2(h);
}
// fast SiLU: x * sigmoid(x) = x * (0.5*tanh(x/2) + 0.5)  (1 MUFU instead of 2)
__device__ __forceinline__ float silu_f(float x) {
    float t;
    asm("tanh.approx.f32 %0, %1;" : "=f"(t) : "f"(0.5f * x));
    return x * fmaf(0.5f, t, 0.5f);
}

// sort idx + derive segment for image (b,t)
__device__ __forceinline__ void seg_params(const int* __restrict__ idx, int b, int t,
                                           int& t0, int& t1, float& a, float& araw) {
    int v[9];
#pragma unroll
    for (int k = 0; k < 9; k++) v[k] = idx[b * 9 + k];
#pragma unroll
    for (int i = 1; i < 9; i++) {
        int key = v[i]; int j = i - 1;
        while (j >= 0 && v[j] > key) { v[j + 1] = v[j]; j--; }
        v[j + 1] = key;
    }
    int cnt = 0;
#pragma unroll
    for (int k = 0; k < 9; k++) cnt += (v[k] <= t);
    int seg = min(max(cnt - 1, 0), 7);
    t0 = v[seg]; t1 = v[seg + 1];
    araw = (float)(t - t0) / (float)max(t1 - t0, 1);
    a = fminf(fmaxf(araw, 0.f), 1.f);
}

// ----------------------------------------------------------------------------
// merged prep: blocks [0,512) kf convert, [512,1024) per-image fold,
//              [1024,1029) layer weight prep
// ----------------------------------------------------------------------------
__global__ __launch_bounds__(256)
void prep_all_kernel(const float* __restrict__ latents, const int* __restrict__ idx,
                     const float* __restrict__ w_in, const float* __restrict__ w1s,
                     const float* __restrict__ w2s, const float* __restrict__ w_out,
                     __half* __restrict__ kf, uint32_t* __restrict__ wfold,
                     float* __restrict__ sfold, uint32_t* __restrict__ wfrag)
{
    const int tid = threadIdx.x;

    if (blockIdx.x < 512) {
        const int fr = blockIdx.x;
        const float* L = latents + (size_t)fr * 8 * HW;
#pragma unroll
        for (int j = 0; j < 4; j++) {
            const int p = tid + j * 256;
            uint32_t w[4];
#pragma unroll
            for (int q = 0; q < 4; q++)
                w[q] = h2u(__floats2half2_rn(L[(2*q) * HW + p], L[(2*q+1) * HW + p]));
            *(uint4*)(kf + ((size_t)fr * HW + p) * 8) = make_uint4(w[0], w[1], w[2], w[3]);
        }
    } else if (blockIdx.x < 1024) {
        const int n = blockIdx.x - 512;
        int t0, t1; float a, araw;
        seg_params(idx, n >> 7, n & 127, t0, t1, a, araw);

        __half* wh = (__half*)(wfold + (size_t)n * 4608);
        for (int i = tid; i < 4608; i += 256) {
            const int o   = i / 72;
            const int r   = i % 72;
            const int tap = r / 8;
            const int ci  = r % 8;
            const float W0 = w_in[(o * 25 + ci) * 9 + tap];
            const float W1 = w_in[(o * 25 + 8 + ci) * 9 + tap];
            const float W2 = w_in[(o * 25 + 16 + ci) * 9 + tap];
            const float U  = (1.f - a) * W0 + W1;
            const float V  = a * W0 + W2;
            const int kz0 = 2 * (ci >> 2) + 8 * ((ci >> 1) & 1) + (ci & 1);
#pragma unroll
            for (int h = 0; h < 2; h++) {
                const int k  = kz0 + 4 * h;
                const int hi = k >> 3, rem = k & 7, tt = rem >> 1, hf = rem & 1;
                const int lane = (o & 7) * 4 + tt;
                const int word = (o >> 5) * 2304 + (tap * 4 + ((o >> 3) & 3)) * 64 + lane * 2 + hi;
                wh[word * 2 + hf] = __float2half(h ? V : U);
            }
        }
        for (int i = tid; i < 576; i += 256) {
            const int o  = i / 9;
            const int cs = i % 9;
            const int cy = cs / 3, cx = cs % 3;
            float sum = 0.f;
#pragma unroll
            for (int dy = 0; dy < 3; dy++) {
                if ((cy == 0 && dy == 0) || (cy == 2 && dy == 2)) continue;
#pragma unroll
                for (int dx = 0; dx < 3; dx++) {
                    if ((cx == 0 && dx == 0) || (cx == 2 && dx == 2)) continue;
                    sum += w_in[(o * 25 + 24) * 9 + dy * 3 + dx];
                }
            }
            sfold[(size_t)n * 576 + cs * 64 + o] = a * sum;
        }
    } else {
        const int layer = blockIdx.x - 1024 + 1;
        const float* w;
        int cin, cout, woff, nwords, chunks, ntb;
        if (layer <= 4) {
            const int blk = (layer - 1) >> 1;
            w = ((layer - 1) & 1) ? (w2s + (size_t)blk * 64 * 64 * 9)
                                  : (w1s + (size_t)blk * 64 * 64 * 9);
            cin = 64; cout = 64; woff = WOFF_HID0 + (layer - 1) * 18432; nwords = 18432; chunks = 36; ntb = 4;
        } else {
            w = w_out; cin = 64; cout = 9;  woff = WOFF_OUT; nwords = 4608; chunks = 36; ntb = 2;
        }

        for (int i = tid; i < nwords; i += 256) wfrag[woff + i] = 0u;
        __syncthreads();

        __half* wh = (__half*)(wfrag);
        const int wtot = cout * cin * 9;
        for (int i = tid; i < wtot; i += 256) {
            const int tap = i % 9;
            const int ci  = (i / 9) % cin;
            const int co  = i / (9 * cin);
            const int cg  = ci >> 5;
            const int kin = ci & 31;
            const int g2  = kin >> 4;
            const int k16 = kin & 15;
            const int chunk = (cg * 9 + tap) * 2 + g2;
            const int hi  = k16 >> 3;
            const int rem = k16 & 7;
            const int tt  = rem >> 1;
            const int hf  = rem & 1;
            const int lane = (co & 7) * 4 + tt;
            int word;
            if (ntb == 4) {
                const int nhalf = co >> 5;
                const int nt4   = (co >> 3) & 3;
                word = woff + nhalf * chunks * 256 + (chunk * 4 + nt4) * 64 + lane * 2 + hi;
            } else {
                const int nt = co >> 3;
                word = woff + (chunk * 2 + nt) * 64 + lane * 2 + hi;
            }
            wh[word * 2 + hf] = __float2half(w[i]);
        }
    }
}

// ----------------------------------------------------------------------------
// conv_in (fused prep): 16 real channels (z0|z1 from kf16), per-image folded
// weights, alpha border correction (Sp in smem), SiLU. Grid (512, 2).
// Epilogue uses uint2 (8B) stores + tanh-based SiLU.
// ----------------------------------------------------------------------------
__global__ __launch_bounds__(256, 2)
void conv_in16(const __half* __restrict__ kf, const uint32_t* __restrict__ wfold,
               const float* __restrict__ sfold, const float* __restrict__ bias,
               __half* __restrict__ out, const int* __restrict__ idx)
{
    constexpr int NTB = 4;
    constexpr int BW  = 9 * NTB * 64;   // 2304 words
    extern __shared__ uint32_t smem[];
    uint32_t* b_s  = smem;
    float*    Sp_s = (float*)(smem + BW);       // 576 floats
    uint32_t* X_s  = smem + BW + 576;

    const int tid   = threadIdx.x;
    const int wid   = tid >> 5;
    const int lane  = tid & 31;
    const int n     = blockIdx.x;
    const int nhalf = blockIdx.y;
    const int tx    = lane >> 2;
    const int kq2   = (lane & 3) * 2;
    const int ch0   = nhalf * 32;

    int t0, t1; float a, araw;
    seg_params(idx, n >> 7, n & 127, t0, t1, a, araw);
    const int fb = n >> 7;
    const char* kf0 = (const char*)(kf + ((size_t)(fb * 128 + t0)) * HW * 8);
    const char* kf1 = (const char*)(kf + ((size_t)(fb * 128 + t1)) * HW * 8);
    const char* kfp = (tid & 1) ? kf1 : kf0;

    const uint32_t bs_u = smem_u32(b_s);
    const uint32_t sp_u = smem_u32(Sp_s);
    const uint32_t xs_u = smem_u32(X_s);

    const uint32_t* wsrc = wfold + (size_t)n * 4608 + nhalf * 2304;
    for (int i = tid; i < BW / 4; i += 256)
        cp_async16(bs_u + i * 16, wsrc + i * 4, 16);
    if (tid < 144)
        cp_async16(sp_u + tid * 16, sfold + (size_t)n * 576 + tid * 4, 16);

    uint32_t s_dst[5];
#pragma unroll
    for (int q = 0; q < 5; q++) {
        const int i = tid + q * 256;
        const int px = i >> 1, part = i & 1;
        s_dst[q] = (uint32_t)(px * 32 + part * 16);
    }

    auto stage_tile = [&](int tile) {
#pragma unroll
        for (int q = 0; q < 5; q++) {
            const int i = tid + q * 256;
            if (q < 4 || tid < 200) {
                const int px = i >> 1;
                const int rr = px / 34;
                const int gx = px - rr * 34 - 1;
                const int gy = tile * 16 - 1 + rr;
                const bool ok = (gx >= 0) && (gx < 32) && (gy >= 0) && (gy < 32)
                                && (i < 1224);
                const int pix = ok ? (gy * 32 + gx) : 0;
                cp_async16(xs_u + tile * 19584 + s_dst[q], kfp + (size_t)pix * 16,
                           ok ? 16u : 0u);
            }
        }
        cp_commit();
    };

    stage_tile(0);
    stage_tile(1);

    float bv[NTB][2];
#pragma unroll
    for (int nt = 0; nt < NTB; nt++) {
        bv[nt][0] = bias[ch0 + nt * 8 + kq2];
        bv[nt][1] = bias[ch0 + nt * 8 + kq2 + 1];
    }

#pragma unroll 1
    for (int tile = 0; tile < 2; tile++) {
        if (tile == 0) cp_wait1(); else cp_wait0();
        __syncthreads();

        float d[4][NTB][4];
#pragma unroll
        for (int f = 0; f < 4; f++)
#pragma unroll
            for (int nt = 0; nt < NTB; nt++)
#pragma unroll
                for (int q = 0; q < 4; q++) d[f][nt][q] = 0.f;

        const uint32_t* Xb = X_s + tile * 4896;

#pragma unroll
        for (int tap = 0; tap < 9; tap++) {
            const int dy = tap / 3, dx = tap - 3 * (tap / 3);
            const uint32_t* A = Xb + ((2 * wid + dy) * 34 + tx + dx) * 8 + kq2;
            const uint2 u0 = *(const uint2*)(A);
            const uint2 u1 = *(const uint2*)(A + 64);
            const uint2 u2 = *(const uint2*)(A + 128);
            const uint2 u3 = *(const uint2*)(A + 192);
            const uint2 u4 = *(const uint2*)(A + 272);
            const uint2 u5 = *(const uint2*)(A + 336);
            const uint2 u6 = *(const uint2*)(A + 400);
            const uint2 u7 = *(const uint2*)(A + 464);
            const uint32_t* bp = b_s + (size_t)tap * NTB * 64 + lane * 2;
#pragma unroll
            for (int nt = 0; nt < NTB; nt++) {
                const uint2 b = *(const uint2*)(bp + nt * 64);
                mma_f16(d[0][nt], u0.x, u1.x, u0.y, u1.y, b.x, b.y);
                mma_f16(d[1][nt], u2.x, u3.x, u2.y, u3.y, b.x, b.y);
                mma_f16(d[2][nt], u4.x, u5.x, u4.y, u5.y, b.x, b.y);
                mma_f16(d[3][nt], u6.x, u7.x, u6.y, u7.y, b.x, b.y);
            }
        }

#pragma unroll
        for (int f = 0; f < 4; f++) {
            const int gy  = tile * 16 + 2 * wid + (f >> 1);
            const int gx0 = ((f & 1) << 4) + tx;
            const int gx1 = gx0 + 8;
            const int cy  = (gy == 0) ? 0 : ((gy == 31) ? 2 : 1);
            const int cx0 = (gx0 == 0) ? 0 : ((gx0 == 31) ? 2 : 1);
            const int cx1 = (gx1 == 31) ? 2 : 1;
            const int base0 = (cy * 3 + cx0) * 64;
            const int base1 = (cy * 3 + cx1) * 64;
            const size_t gp0 = (size_t)n * HW + gy * 32 + gx0;
            const size_t gp1 = gp0 + 8;
#pragma unroll
            for (int gp16 = 0; gp16 < 2; gp16++) {
                const int nt0 = 2 * gp16, nt1 = nt0 + 1;
                const int c0 = ch0 + nt0 * 8 + kq2;
                const int c1 = c0 + 8;
                const int g16 = (ch0 >> 4) + gp16;
                float v00 = silu_f(d[f][nt0][0] + bv[nt0][0] + Sp_s[base0 + c0]);
                float v01 = silu_f(d[f][nt0][1] + bv[nt0][1] + Sp_s[base0 + c0 + 1]);
                float v02 = silu_f(d[f][nt1][0] + bv[nt1][0] + Sp_s[base0 + c1]);
                float v03 = silu_f(d[f][nt1][1] + bv[nt1][1] + Sp_s[base0 + c1 + 1]);
                float v10 = silu_f(d[f][nt0][2] + bv[nt0][0] + Sp_s[base1 + c0]);
                float v11 = silu_f(d[f][nt0][3] + bv[nt0][1] + Sp_s[base1 + c0 + 1]);
                float v12 = silu_f(d[f][nt1][2] + bv[nt1][0] + Sp_s[base1 + c1]);
                float v13 = silu_f(d[f][nt1][3] + bv[nt1][1] + Sp_s[base1 + c1 + 1]);
                const size_t w0 = gp0 * 64 + g16 * 16 + kq2 * 2;   // half units
                const size_t w1 = gp1 * 64 + g16 * 16 + kq2 * 2;
                uint2 s0, s1;
                s0.x = h2u(__floats2half2_rn(v00, v01));
                s0.y = h2u(__floats2half2_rn(v02, v03));
                s1.x = h2u(__floats2half2_rn(v10, v11));
                s1.y = h2u(__floats2half2_rn(v12, v13));
                *(uint2*)(out + w0) = s0;
                *(uint2*)(out + w1) = s1;
            }
        }
    }
}

// ----------------------------------------------------------------------------
// hidden/out conv: mma.sync m16n8k16, M64xN=NTB*8 per warp, 3-buffer pipeline.
// TSPLIT: blockIdx.y = 16-row tile (4 stages). FINAL fuses z_hat/conf.
// MINB: min blocks per SM. F16OUT epilogue uses uint2 (8B) loads/stores.
// ----------------------------------------------------------------------------
template<int NTB, bool SILU, bool RESID, bool FINAL, bool TSPLIT, int MINB>
__global__ __launch_bounds__(256, MINB)
void conv_mma(const void* __restrict__ in_v, const uint32_t* __restrict__ wfrag,
              const float* __restrict__ bias, void* __restrict__ out_v,
              const void* __restrict__ resid_v,
              const float* __restrict__ latents, const int* __restrict__ idx)
{
    constexpr int CIN    = 64;
    constexpr int CHUNKS = 36;
    constexpr int BW     = CHUNKS * NTB * 64;
    constexpr int SLABS  = 4;
    constexpr int NSTAGE = TSPLIT ? SLABS : 2 * SLABS;
    constexpr bool F16OUT = (NTB == 4);

    extern __shared__ uint32_t smem[];
    uint32_t* b_s = smem;
    uint32_t* X_s = smem + BW;

    const int tid   = threadIdx.x;
    const int wid   = tid >> 5;
    const int lane  = tid & 31;
    const int n     = blockIdx.x;
    const int nhalf = TSPLIT ? 0 : blockIdx.y;
    const int tfix  = TSPLIT ? blockIdx.y : 0;
    const int tx    = lane >> 2;
    const int kq2   = (lane & 3) * 2;
    const int ch0   = F16OUT ? nhalf * 32 : 0;

    const uint32_t bs_u = smem_u32(b_s);
    const uint32_t xs_u = smem_u32(X_s);
    const char* in_b = (const char*)in_v + (size_t)n * HW * CIN * 2;

    float fs_a = 0.f, fs_s = 0.f;
    bool  fs_int = false;
    const float* L0f = nullptr;
    const float* L1f = nullptr;
    if constexpr (FINAL) {
        int t0, t1; float araw;
        seg_params(idx, n >> 7, n & 127, t0, t1, fs_a, araw);
        fs_s   = fs_a * (1.f - fs_a);
        fs_int = (araw > 0.f) && (araw < 1.f);
        L0f = latents + ((size_t)((n >> 7) * 128 + t0)) * 8 * HW;
        L1f = latents + ((size_t)((n >> 7) * 128 + t1)) * 8 * HW;
    }

    const uint32_t* wsrc = wfrag + (size_t)nhalf * CHUNKS * NTB * 64;
    for (int i = tid; i < BW / 4; i += 256)
        cp_async16(bs_u + i * 16, wsrc + i * 4, 16);

    uint32_t s_dst[5];
#pragma unroll
    for (int q = 0; q < 5; q++) {
        const int i = tid + q * 256;
        const int px = i >> 1, part = i & 1;
        s_dst[q] = (uint32_t)(px * 32 + part * 16);
    }
    int s_src[5];
    uint32_t okb = 0;
    int cached_tile = -1;

    auto stage_slab = [&](int s) {
        const int tile = TSPLIT ? tfix : (s / SLABS);
        const int k    = s & (SLABS - 1);
        if (tile != cached_tile) {
            cached_tile = tile;
            okb = 0;
#pragma unroll
            for (int q = 0; q < 5; q++) {
                const int i = tid + q * 256;
                const int px = i >> 1, part = i & 1;
                const int rr = px / 34;
                const int gx = px - rr * 34 - 1;
                const int gy = tile * 16 - 1 + rr;
                const bool ok = (gx >= 0) && (gx < 32) && (gy >= 0) && (gy < 32)
                                && (i < 1224);
                const int pix = ok ? (gy * 32 + gx) : 0;
                s_src[q] = pix * CIN * 2 + part * 16;
                okb |= (ok ? 1u : 0u) << q;
            }
        }
        const uint32_t xoff = (uint32_t)((s % 3) * 19584);
#pragma unroll
        for (int q = 0; q < 5; q++) {
            if (q < 4 || tid < 200)
                cp_async16(xs_u + xoff + s_dst[q], in_b + s_src[q] + k * 32,
                           ((okb >> q) & 1) ? 16u : 0u);
        }
        cp_commit();
    };

    stage_slab(0);
    stage_slab(1);

    float bv[NTB][2];
#pragma unroll
    for (int nt = 0; nt < NTB; nt++) {
        const int bi = ch0 + nt * 8 + kq2;
        bv[nt][0] = (F16OUT || bi     < 9) ? bias[bi]     : 0.f;
        bv[nt][1] = (F16OUT || bi + 1 < 9) ? bias[bi + 1] : 0.f;
    }

    float d[4][NTB][4];

#pragma unroll 1
    for (int s = 0; s < NSTAGE; s++) {
        const int tile = TSPLIT ? tfix : (s / SLABS);
        const int k    = s & (SLABS - 1);

        if (s + 1 < NSTAGE) cp_wait1(); else cp_wait0();
        __syncthreads();
        if (s + 2 < NSTAGE) stage_slab(s + 2);

        if (k == 0) {
#pragma unroll
            for (int f = 0; f < 4; f++)
#pragma unroll
                for (int nt = 0; nt < NTB; nt++)
#pragma unroll
                    for (int q = 0; q < 4; q++) d[f][nt][q] = 0.f;
        }

        const uint32_t* Xb = X_s + (s % 3) * 4896;
        const int cbase = (k >> 1) * 18 + (k & 1);

#pragma unroll
        for (int tap = 0; tap < 9; tap++) {
            const int dy = tap / 3, dx = tap - 3 * (tap / 3);
            const uint32_t* A = Xb + ((2 * wid + dy) * 34 + tx + dx) * 8 + kq2;
            const uint2 u0 = *(const uint2*)(A);
            const uint2 u1 = *(const uint2*)(A + 64);
            const uint2 u2 = *(const uint2*)(A + 128);
            const uint2 u3 = *(const uint2*)(A + 192);
            const uint2 u4 = *(const uint2*)(A + 272);
            const uint2 u5 = *(const uint2*)(A + 336);
            const uint2 u6 = *(const uint2*)(A + 400);
            const uint2 u7 = *(const uint2*)(A + 464);
            const uint32_t* bp = b_s + (size_t)(cbase + tap * 2) * NTB * 64 + lane * 2;
#pragma unroll
            for (int nt = 0; nt < NTB; nt++) {
                const uint2 b = *(const uint2*)(bp + nt * 64);
                mma_f16(d[0][nt], u0.x, u1.x, u0.y, u1.y, b.x, b.y);
                mma_f16(d[1][nt], u2.x, u3.x, u2.y, u3.y, b.x, b.y);
                mma_f16(d[2][nt], u4.x, u5.x, u4.y, u5.y, b.x, b.y);
                mma_f16(d[3][nt], u6.x, u7.x, u6.y, u7.y, b.x, b.y);
            }
        }

        if (k == SLABS - 1) {
#pragma unroll
            for (int f = 0; f < 4; f++) {
                const int gy = tile * 16 + 2 * wid + (f >> 1);
                const int gx = ((f & 1) << 4) + tx;
                const int p0i = gy * 32 + gx;
                const size_t gp0 = (size_t)n * HW + p0i;
                const size_t gp1 = gp0 + 8;

                if constexpr (FINAL) {
                    float* outp = (float*)out_v;
#pragma unroll
                    for (int e = 0; e < 2; e++) {
                        const int c = kq2 + e;
                        const float r0 = d[f][0][e]     + bv[0][e];
                        const float r1 = d[f][0][2 + e] + bv[0][e];
                        const float zb0 = (1.f - fs_a) * L0f[c * HW + p0i]
                                        + fs_a * L1f[c * HW + p0i];
                        const float zb1 = (1.f - fs_a) * L0f[c * HW + p0i + 8]
                                        + fs_a * L1f[c * HW + p0i + 8];
                        outp[((size_t)n * 8 + c) * HW + p0i]     = zb0 + fs_s * r0;
                        outp[((size_t)n * 8 + c) * HW + p0i + 8] = zb1 + fs_s * r1;
                    }
                    if (kq2 == 0) {
                        const float l0 = d[f][1][0] + bv[1][0];
                        const float l1 = d[f][1][2] + bv[1][0];
                        float c0 = 1.f, c1 = 1.f;
                        if (fs_int) {
                            c0 = 1.f - __fdividef(1.f, 1.f + __expf(-l0));
                            c1 = 1.f - __fdividef(1.f, 1.f + __expf(-l1));
                            c0 = fminf(fmaxf(c0, 0.f), 1.f);
                            c1 = fminf(fmaxf(c1, 0.f), 1.f);
                        }
                        float* cf = outp + (size_t)NIMG * 8 * HW + (size_t)n * HW;
                        cf[p0i]     = c0;
                        cf[p0i + 8] = c1;
                    }
                } else {
                    __half* oh = (__half*)out_v;
#pragma unroll
                    for (int gp16 = 0; gp16 < NTB / 2; gp16++) {
                        const int nt0 = 2 * gp16, nt1 = nt0 + 1;
                        const int g16 = (ch0 >> 4) + gp16;
                        float v00 = d[f][nt0][0] + bv[nt0][0];
                        float v01 = d[f][nt0][1] + bv[nt0][1];
                        float v02 = d[f][nt1][0] + bv[nt1][0];
                        float v03 = d[f][nt1][1] + bv[nt1][1];
                        float v10 = d[f][nt0][2] + bv[nt0][0];
                        float v11 = d[f][nt0][3] + bv[nt0][1];
                        float v12 = d[f][nt1][2] + bv[nt1][0];
                        float v13 = d[f][nt1][3] + bv[nt1][1];
                        if (SILU) {
                            v00 = silu_f(v00); v01 = silu_f(v01);
                            v02 = silu_f(v02); v03 = silu_f(v03);
                            v10 = silu_f(v10); v11 = silu_f(v11);
                            v12 = silu_f(v12); v13 = silu_f(v13);
                        }
                        const size_t w0 = gp0 * 64 + g16 * 16 + kq2 * 2;  // half units
                        const size_t w1 = gp1 * 64 + g16 * 16 + kq2 * 2;
                        if (RESID) {
                            const uint2 r0 = *(const uint2*)((const __half*)resid_v + w0);
                            const uint2 r1 = *(const uint2*)((const __half*)resid_v + w1);
                            const float2 a0 = u2f2(r0.x), a1 = u2f2(r0.y);
                            const float2 a2 = u2f2(r1.x), a3 = u2f2(r1.y);
                            v00 += a0.x; v01 += a0.y; v02 += a1.x; v03 += a1.y;
                            v10 += a2.x; v11 += a2.y; v12 += a3.x; v13 += a3.y;
                        }
                        uint2 s0, s1;
                        s0.x = h2u(__floats2half2_rn(v00, v01));
                        s0.y = h2u(__floats2half2_rn(v02, v03));
                        s1.x = h2u(__floats2half2_rn(v10, v11));
                        s1.y = h2u(__floats2half2_rn(v12, v13));
                        *(uint2*)(oh + w0) = s0;
                        *(uint2*)(oh + w1) = s1;
                    }
                }
            }
        }
    }
}

// ----------------------------------------------------------------------------
// launch
// ----------------------------------------------------------------------------
extern "C" void kernel_launch(void* const* d_in, const int* in_sizes, int n_in,
                              void* d_out, int out_size)
{
    const float* latents = (const float*)d_in[0];
    const int*   idx     = (const int*)d_in[1];
    const float* w_in    = (const float*)d_in[2];
    const float* b_in    = (const float*)d_in[3];
    const float* w1s     = (const float*)d_in[4];
    const float* b1s     = (const float*)d_in[5];
    const float* w2s     = (const float*)d_in[6];
    const float* b2s     = (const float*)d_in[7];
    const float* w_out   = (const float*)d_in[8];
    const float* b_out   = (const float*)d_in[9];
    float* outp = (float*)d_out;

    __half *kf, *h, *tmp;
    uint32_t *wfrag, *wfold;
    float* sfold;
    cudaGetSymbolAddress((void**)&kf,    g_kf16);
    cudaGetSymbolAddress((void**)&h,     g_h);
    cudaGetSymbolAddress((void**)&tmp,   g_tmp);
    cudaGetSymbolAddress((void**)&wfrag, g_wfrag);
    cudaGetSymbolAddress((void**)&wfold, g_wfold);
    cudaGetSymbolAddress((void**)&sfold, g_sfold);

    constexpr int SM_IN16 = ( 2304 + 576 + 2 * 4896) * 4;   // 50,688 (2 buffers)
    constexpr int SM_HID  = ( 9216 + 3 * 4896) * 4;         // 95,616
    constexpr int SM_OUT  = ( 4608 + 3 * 4896) * 4;         // 77,184

    cudaFuncSetAttribute(conv_in16,
                         cudaFuncAttributeMaxDynamicSharedMemorySize, SM_IN16);
    cudaFuncSetAttribute(conv_mma<4, true,  false, false, false, 2>,
                         cudaFuncAttributeMaxDynamicSharedMemorySize, SM_HID);
    cudaFuncSetAttribute(conv_mma<4, false, true,  false, false, 2>,
                         cudaFuncAttributeMaxDynamicSharedMemorySize, SM_HID);
    cudaFuncSetAttribute(conv_mma<2, false, false, true,  true,  3>,
                         cudaFuncAttributeMaxDynamicSharedMemorySize, SM_OUT);

    prep_all_kernel<<<1029, 256>>>(latents, idx, w_in, w1s, w2s, w_out,
                                   kf, wfold, sfold, wfrag);

    // conv_in (fused prep): z0|z1 16ch -> 64, SiLU
    conv_in16<<<dim3(NIMG, 2), 256, SM_IN16>>>(kf, wfold, sfold, b_in, h, idx);

    for (int blk = 0; blk < 2; blk++) {
        const float* b1 = b1s + blk * 64;
        const float* b2 = b2s + blk * 64;
        conv_mma<4, true, false, false, false, 2><<<dim3(NIMG, 2), 256, SM_HID>>>(
            h, wfrag + WOFF_HID0 + (2 * blk) * 18432, b1, tmp, nullptr, nullptr, nullptr);
        conv_mma<4, false, true, false, false, 2><<<dim3(NIMG, 2), 256, SM_HID>>>(
            tmp, wfrag + WOFF_HID0 + (2 * blk + 1) * 18432, b2, h, h, nullptr, nullptr);
    }

    // conv_out: 64 -> 9, fused finalize, tile-split grid (512, 2), 3 CTAs/SM
    conv_mma<2, false, false, true, true, 3><<<dim3(NIMG, 2), 256, SM_OUT>>>(
        h, wfrag + WOFF_OUT, b_out, outp, nullptr, latents, idx);
}